// round 2
// baseline (speedup 1.0000x reference)
#include <cuda_runtime.h>
#include <cuda_bf16.h>

#define BATCH   2
#define S_LEN   2048
#define DMODEL  1024
#define NHEAD   16
#define DHEAD   64
#define TRIPLE  (3 * DMODEL)   // 3072
#define MTOT    (BATCH * S_LEN) // 4096

// Scratch (allocation-free: __device__ globals)
__device__ float g_qkv[(size_t)MTOT * TRIPLE];   // [M, 3*D] = [b,s][(t*16+h)*64+d]
__device__ float g_ctx[(size_t)MTOT * DMODEL];   // [M, D]

// ---------------------------------------------------------------------------
// GEMM: C[m,n] = sum_k A[m*K+k] * B[n*K+k]  (+ bias[n])
// BM=BN=128, BK=8, 256 threads, 8x8 microtile. M%128==0, N%128==0, K%8==0.
// ---------------------------------------------------------------------------
template <bool BIAS>
__global__ void __launch_bounds__(256) gemm_nt(const float* __restrict__ A,
                                               const float* __restrict__ B,
                                               const float* __restrict__ bias,
                                               float* __restrict__ C,
                                               int M, int N, int K)
{
    __shared__ float As[8][128];
    __shared__ float Bs[8][128];

    const int tid = threadIdx.x;
    const int bm = blockIdx.y * 128;
    const int bn = blockIdx.x * 128;
    const int tx = tid & 15, ty = tid >> 4;
    const int row0 = ty * 8, col0 = tx * 8;

    const int lrow = tid >> 1;          // 0..127
    const int lk   = (tid & 1) * 4;     // 0 or 4

    const float* Aptr = A + (size_t)(bm + lrow) * K + lk;
    const float* Bptr = B + (size_t)(bn + lrow) * K + lk;

    float acc[8][8];
    #pragma unroll
    for (int i = 0; i < 8; i++)
        #pragma unroll
        for (int j = 0; j < 8; j++) acc[i][j] = 0.f;

    for (int k0 = 0; k0 < K; k0 += 8) {
        float4 a4 = *(const float4*)(Aptr + k0);
        float4 b4 = *(const float4*)(Bptr + k0);
        __syncthreads();
        As[lk + 0][lrow] = a4.x; As[lk + 1][lrow] = a4.y;
        As[lk + 2][lrow] = a4.z; As[lk + 3][lrow] = a4.w;
        Bs[lk + 0][lrow] = b4.x; Bs[lk + 1][lrow] = b4.y;
        Bs[lk + 2][lrow] = b4.z; Bs[lk + 3][lrow] = b4.w;
        __syncthreads();
        #pragma unroll
        for (int k = 0; k < 8; k++) {
            float ra[8], rb[8];
            *(float4*)(ra)     = *(const float4*)&As[k][row0];
            *(float4*)(ra + 4) = *(const float4*)&As[k][row0 + 4];
            *(float4*)(rb)     = *(const float4*)&Bs[k][col0];
            *(float4*)(rb + 4) = *(const float4*)&Bs[k][col0 + 4];
            #pragma unroll
            for (int i = 0; i < 8; i++)
                #pragma unroll
                for (int j = 0; j < 8; j++)
                    acc[i][j] = fmaf(ra[i], rb[j], acc[i][j]);
        }
    }

    #pragma unroll
    for (int i = 0; i < 8; i++) {
        size_t m = (size_t)(bm + row0 + i);
        #pragma unroll
        for (int j = 0; j < 8; j += 4) {
            float4 v = make_float4(acc[i][j], acc[i][j+1], acc[i][j+2], acc[i][j+3]);
            if (BIAS) {
                int n = bn + col0 + j;
                v.x += bias[n]; v.y += bias[n+1]; v.z += bias[n+2]; v.w += bias[n+3];
            }
            *(float4*)&C[m * N + bn + col0 + j] = v;
        }
    }
}

// ---------------------------------------------------------------------------
// Flash attention (causal), fp32, 64x64 tiles.
// grid: (S/64, B*H), block 256 = 16x16 threads, each owns a 4x4 microtile.
// smem (dynamic, pad=68 -> all float4 accesses 16B-aligned):
//   Qs[r][d], KsT[d][c], Vs[c][d], Ps[r][c].
// ---------------------------------------------------------------------------
#define PAD 68
#define ATTN_SMEM (4 * 64 * PAD * 4)

__global__ void __launch_bounds__(256) attn_kernel(const float* __restrict__ qkv,
                                                   float* __restrict__ ctx)
{
    extern __shared__ float sm[];
    float* Qs  = sm;                 // [64][PAD] (r, d)
    float* KsT = sm + 64 * PAD;      // [64][PAD] (d, c)
    float* Vs  = sm + 2 * 64 * PAD;  // [64][PAD] (c, d)
    float* Ps  = sm + 3 * 64 * PAD;  // [64][PAD] (r, c)

    const int mblk = blockIdx.x;           // 0..31
    const int bh   = blockIdx.y;           // 0..31
    const int b = bh >> 4, h = bh & 15;
    const int tid = threadIdx.x;
    const int tx = tid & 15, ty = tid >> 4;
    const int r0 = ty * 4, c0 = tx * 4;
    const int m0 = mblk * 64;
    const float scale = 0.125f;            // 1/sqrt(64)

    // Load Q tile (coalesced: 64 rows x 16 float4)
    #pragma unroll
    for (int l = 0; l < 4; l++) {
        int idx = tid + l * 256;
        int row = idx >> 4, dc = (idx & 15) << 2;
        float4 v = *(const float4*)&qkv[(size_t)(b * S_LEN + m0 + row) * TRIPLE + h * DHEAD + dc];
        *(float4*)&Qs[row * PAD + dc] = v;
    }

    float acc[4][4];
    float m_i[4], l_i[4];
    #pragma unroll
    for (int i = 0; i < 4; i++) {
        m_i[i] = -1e30f; l_i[i] = 0.f;
        #pragma unroll
        for (int j = 0; j < 4; j++) acc[i][j] = 0.f;
    }

    const int nblocks = mblk + 1;   // causal
    for (int nb = 0; nb < nblocks; nb++) {
        const int n0 = nb * 64;
        __syncthreads();   // prev iter's Ps/Vs reads done; Qs visible on iter 0
        // Load K (transposed to d-major) and V
        #pragma unroll
        for (int l = 0; l < 4; l++) {
            int idx = tid + l * 256;
            int c = idx >> 4, dc = (idx & 15) << 2;
            size_t base = (size_t)(b * S_LEN + n0 + c) * TRIPLE + h * DHEAD + dc;
            float4 kv = *(const float4*)&qkv[base + DMODEL];
            KsT[(dc + 0) * PAD + c] = kv.x;
            KsT[(dc + 1) * PAD + c] = kv.y;
            KsT[(dc + 2) * PAD + c] = kv.z;
            KsT[(dc + 3) * PAD + c] = kv.w;
            float4 vv = *(const float4*)&qkv[base + 2 * DMODEL];
            *(float4*)&Vs[c * PAD + dc] = vv;
        }
        __syncthreads();

        // S = Q K^T (64x64x64)
        float s[4][4];
        #pragma unroll
        for (int i = 0; i < 4; i++)
            #pragma unroll
            for (int j = 0; j < 4; j++) s[i][j] = 0.f;
        #pragma unroll 8
        for (int d = 0; d < 64; d++) {
            float rq0 = Qs[(r0 + 0) * PAD + d];
            float rq1 = Qs[(r0 + 1) * PAD + d];
            float rq2 = Qs[(r0 + 2) * PAD + d];
            float rq3 = Qs[(r0 + 3) * PAD + d];
            float4 rk = *(const float4*)&KsT[d * PAD + c0];
            s[0][0] = fmaf(rq0, rk.x, s[0][0]); s[0][1] = fmaf(rq0, rk.y, s[0][1]);
            s[0][2] = fmaf(rq0, rk.z, s[0][2]); s[0][3] = fmaf(rq0, rk.w, s[0][3]);
            s[1][0] = fmaf(rq1, rk.x, s[1][0]); s[1][1] = fmaf(rq1, rk.y, s[1][1]);
            s[1][2] = fmaf(rq1, rk.z, s[1][2]); s[1][3] = fmaf(rq1, rk.w, s[1][3]);
            s[2][0] = fmaf(rq2, rk.x, s[2][0]); s[2][1] = fmaf(rq2, rk.y, s[2][1]);
            s[2][2] = fmaf(rq2, rk.z, s[2][2]); s[2][3] = fmaf(rq2, rk.w, s[2][3]);
            s[3][0] = fmaf(rq3, rk.x, s[3][0]); s[3][1] = fmaf(rq3, rk.y, s[3][1]);
            s[3][2] = fmaf(rq3, rk.z, s[3][2]); s[3][3] = fmaf(rq3, rk.w, s[3][3]);
        }

        // scale + causal mask (diagonal block only)
        const bool diag = (nb == mblk);
        #pragma unroll
        for (int i = 0; i < 4; i++)
            #pragma unroll
            for (int j = 0; j < 4; j++) {
                s[i][j] *= scale;
                if (diag && (n0 + c0 + j) > (m0 + r0 + i)) s[i][j] = -1e30f;
            }

        // Online softmax: row max + sum via width-16 shfl (lanes 0-15 share ty)
        float mnew[4], rs[4], alpha[4];
        #pragma unroll
        for (int i = 0; i < 4; i++) {
            float mx = fmaxf(fmaxf(s[i][0], s[i][1]), fmaxf(s[i][2], s[i][3]));
            #pragma unroll
            for (int off = 8; off > 0; off >>= 1)
                mx = fmaxf(mx, __shfl_xor_sync(0xffffffffu, mx, off, 16));
            mnew[i] = mx;
        }
        #pragma unroll
        for (int i = 0; i < 4; i++) {
            float mi2 = fmaxf(m_i[i], mnew[i]);
            alpha[i] = __expf(m_i[i] - mi2);
            m_i[i] = mi2;
            float r = 0.f;
            #pragma unroll
            for (int j = 0; j < 4; j++) {
                float p = __expf(s[i][j] - mi2);
                s[i][j] = p;
                r += p;
            }
            #pragma unroll
            for (int off = 8; off > 0; off >>= 1)
                r += __shfl_xor_sync(0xffffffffu, r, off, 16);
            rs[i] = r;
        }
        #pragma unroll
        for (int i = 0; i < 4; i++) {
            l_i[i] = l_i[i] * alpha[i] + rs[i];
            #pragma unroll
            for (int j = 0; j < 4; j++) acc[i][j] *= alpha[i];
        }

        // store P
        #pragma unroll
        for (int i = 0; i < 4; i++)
            *(float4*)&Ps[(r0 + i) * PAD + c0] =
                make_float4(s[i][0], s[i][1], s[i][2], s[i][3]);
        __syncthreads();

        // acc += P V  (64x64x64)
        #pragma unroll 8
        for (int c = 0; c < 64; c++) {
            float rp0 = Ps[(r0 + 0) * PAD + c];
            float rp1 = Ps[(r0 + 1) * PAD + c];
            float rp2 = Ps[(r0 + 2) * PAD + c];
            float rp3 = Ps[(r0 + 3) * PAD + c];
            float4 rv = *(const float4*)&Vs[c * PAD + c0];
            acc[0][0] = fmaf(rp0, rv.x, acc[0][0]); acc[0][1] = fmaf(rp0, rv.y, acc[0][1]);
            acc[0][2] = fmaf(rp0, rv.z, acc[0][2]); acc[0][3] = fmaf(rp0, rv.w, acc[0][3]);
            acc[1][0] = fmaf(rp1, rv.x, acc[1][0]); acc[1][1] = fmaf(rp1, rv.y, acc[1][1]);
            acc[1][2] = fmaf(rp1, rv.z, acc[1][2]); acc[1][3] = fmaf(rp1, rv.w, acc[1][3]);
            acc[2][0] = fmaf(rp2, rv.x, acc[2][0]); acc[2][1] = fmaf(rp2, rv.y, acc[2][1]);
            acc[2][2] = fmaf(rp2, rv.z, acc[2][2]); acc[2][3] = fmaf(rp2, rv.w, acc[2][3]);
            acc[3][0] = fmaf(rp3, rv.x, acc[3][0]); acc[3][1] = fmaf(rp3, rv.y, acc[3][1]);
            acc[3][2] = fmaf(rp3, rv.z, acc[3][2]); acc[3][3] = fmaf(rp3, rv.w, acc[3][3]);
        }
    }

    // Write ctx[(b,s), h*64+d] normalized by l_i
    #pragma unroll
    for (int i = 0; i < 4; i++) {
        float inv = 1.f / l_i[i];
        float4 o = make_float4(acc[i][0] * inv, acc[i][1] * inv,
                               acc[i][2] * inv, acc[i][3] * inv);
        *(float4*)&ctx[(size_t)(b * S_LEN + m0 + r0 + i) * DMODEL + h * DHEAD + c0] = o;
    }
}

// ---------------------------------------------------------------------------
extern "C" void kernel_launch(void* const* d_in, const int* in_sizes, int n_in,
                              void* d_out, int out_size)
{
    const float* x      = (const float*)d_in[0];  // [2,2048,1024]
    const float* w_qkv  = (const float*)d_in[1];  // [3072,1024]
    const float* w_proj = (const float*)d_in[2];  // [1024,1024]
    const float* b_proj = (const float*)d_in[3];  // [1024]
    float* out = (float*)d_out;                   // [2,2048,1024]

    float *qkv, *ctx;
    cudaGetSymbolAddress((void**)&qkv, g_qkv);
    cudaGetSymbolAddress((void**)&ctx, g_ctx);

    cudaFuncSetAttribute(attn_kernel, cudaFuncAttributeMaxDynamicSharedMemorySize, ATTN_SMEM);

    // 1) QKV projection: [4096,3072] = x[4096,1024] @ w_qkv^T
    {
        dim3 grid(TRIPLE / 128, MTOT / 128);
        gemm_nt<false><<<grid, 256>>>(x, w_qkv, nullptr, qkv, MTOT, TRIPLE, DMODEL);
    }
    // 2) Causal flash attention
    {
        dim3 grid(S_LEN / 64, BATCH * NHEAD);
        attn_kernel<<<grid, 256, ATTN_SMEM>>>(qkv, ctx);
    }
    // 3) Output projection with bias
    {
        dim3 grid(DMODEL / 128, MTOT / 128);
        gemm_nt<true><<<grid, 256>>>(ctx, w_proj, b_proj, out, MTOT, DMODEL, DMODEL);
    }
}

// round 4
// speedup vs baseline: 1.5222x; 1.5222x over previous
#include <cuda_runtime.h>
#include <cuda_bf16.h>
#include <cstdint>

#define BATCH   2
#define S_LEN   2048
#define DMODEL  1024
#define NHEAD   16
#define DHEAD   64
#define TRIPLE  (3 * DMODEL)    // 3072
#define MTOT    (BATCH * S_LEN) // 4096

// ---------------------------------------------------------------------------
// Scratch (allocation-free: __device__ globals)
// ---------------------------------------------------------------------------
__device__ float g_qkv[(size_t)MTOT * TRIPLE];   // fp32 QKV output
__device__ float g_ctx[(size_t)MTOT * DMODEL];   // fp32 attention output

__device__ __nv_bfloat16 g_xhi[(size_t)MTOT * DMODEL];
__device__ __nv_bfloat16 g_xlo[(size_t)MTOT * DMODEL];
__device__ __nv_bfloat16 g_wqh[(size_t)TRIPLE * DMODEL];
__device__ __nv_bfloat16 g_wql[(size_t)TRIPLE * DMODEL];
__device__ __nv_bfloat16 g_chi[(size_t)MTOT * DMODEL];
__device__ __nv_bfloat16 g_clo[(size_t)MTOT * DMODEL];
__device__ __nv_bfloat16 g_wph[(size_t)DMODEL * DMODEL];
__device__ __nv_bfloat16 g_wpl[(size_t)DMODEL * DMODEL];

// ---------------------------------------------------------------------------
// PTX helpers (Ampere-class: cp.async + ldmatrix + mma.sync — legal on sm_103)
// ---------------------------------------------------------------------------
__device__ __forceinline__ void cp_async16(uint32_t dst, const void* src) {
    asm volatile("cp.async.cg.shared.global [%0], [%1], 16;"
                 :: "r"(dst), "l"(__cvta_generic_to_global(src)));
}
__device__ __forceinline__ void cp_commit() {
    asm volatile("cp.async.commit_group;" ::: "memory");
}
template <int N> __device__ __forceinline__ void cp_wait() {
    asm volatile("cp.async.wait_group %0;" :: "n"(N) : "memory");
}
__device__ __forceinline__ void ldsm_x4(uint32_t* r, uint32_t addr) {
    asm volatile("ldmatrix.sync.aligned.m8n8.x4.shared.b16 {%0,%1,%2,%3}, [%4];"
                 : "=r"(r[0]), "=r"(r[1]), "=r"(r[2]), "=r"(r[3]) : "r"(addr));
}
__device__ __forceinline__ void ldsm_x2(uint32_t* r, uint32_t addr) {
    asm volatile("ldmatrix.sync.aligned.m8n8.x2.shared.b16 {%0,%1}, [%2];"
                 : "=r"(r[0]), "=r"(r[1]) : "r"(addr));
}
__device__ __forceinline__ void mma_bf16(float* d, const uint32_t* a, const uint32_t* b) {
    asm volatile("mma.sync.aligned.m16n8k16.row.col.f32.bf16.bf16.f32 "
                 "{%0,%1,%2,%3}, {%4,%5,%6,%7}, {%8,%9}, {%0,%1,%2,%3};"
                 : "+f"(d[0]), "+f"(d[1]), "+f"(d[2]), "+f"(d[3])
                 : "r"(a[0]), "r"(a[1]), "r"(a[2]), "r"(a[3]), "r"(b[0]), "r"(b[1]));
}

// ---------------------------------------------------------------------------
// fp32 -> (hi, lo) bf16 split, 4 elems/thread
// ---------------------------------------------------------------------------
__global__ void __launch_bounds__(256) split_fp32(const float* __restrict__ in,
                                                  __nv_bfloat16* __restrict__ hi,
                                                  __nv_bfloat16* __restrict__ lo) {
    int i = blockIdx.x * 256 + threadIdx.x;
    float4 v = ((const float4*)in)[i];
    __nv_bfloat16 h0 = __float2bfloat16(v.x);
    __nv_bfloat16 h1 = __float2bfloat16(v.y);
    __nv_bfloat16 h2 = __float2bfloat16(v.z);
    __nv_bfloat16 h3 = __float2bfloat16(v.w);
    __nv_bfloat16 l0 = __float2bfloat16(v.x - __bfloat162float(h0));
    __nv_bfloat16 l1 = __float2bfloat16(v.y - __bfloat162float(h1));
    __nv_bfloat16 l2 = __float2bfloat16(v.z - __bfloat162float(h2));
    __nv_bfloat16 l3 = __float2bfloat16(v.w - __bfloat162float(h3));
    __nv_bfloat162* H = (__nv_bfloat162*)hi;
    __nv_bfloat162* L = (__nv_bfloat162*)lo;
    H[2 * i]     = __nv_bfloat162(h0, h1);
    H[2 * i + 1] = __nv_bfloat162(h2, h3);
    L[2 * i]     = __nv_bfloat162(l0, l1);
    L[2 * i + 1] = __nv_bfloat162(l2, l3);
}

// ---------------------------------------------------------------------------
// mma.sync split-bf16 GEMM: C[m,n] = sum_k A[m,k]*B[n,k] (+bias[n]) in ~fp32.
// 128x128x32 CTA tile, 8 warps as 2(m)x4(n), warp tile 64x32.
// smem rows padded to 80B (16B aligned). 2-stage cp.async pipeline.
// ---------------------------------------------------------------------------
#define GBM 128
#define GBN 128
#define GBK 32
#define ROWB 80                          // bytes per padded smem row (32 bf16 + pad)
#define TILEB (128 * ROWB)               // 10240 per operand tile
#define STAGEB (4 * TILEB)               // Ah, Al, Bh, Bl
#define GEMM_SMEM (2 * STAGEB)           // 81920

template <bool BIAS>
__global__ void __launch_bounds__(256)
mma_gemm(const __nv_bfloat16* __restrict__ Ah, const __nv_bfloat16* __restrict__ Al,
         const __nv_bfloat16* __restrict__ Bh, const __nv_bfloat16* __restrict__ Bl,
         const float* __restrict__ bias, float* __restrict__ C,
         int M, int N, int K)
{
    extern __shared__ char smem[];
    const uint32_t sb = (uint32_t)__cvta_generic_to_shared(smem);
    const int tid = threadIdx.x, wid = tid >> 5, lane = tid & 31;
    const int wm = wid >> 2, wn = wid & 3;          // warp grid 2x4
    const int bm = blockIdx.y * GBM, bn = blockIdx.x * GBN;
    const int NK = K / GBK;

    auto load_stage = [&](int s, int kc) {
        uint32_t base = sb + s * STAGEB;
        int k0 = kc * GBK;
        #pragma unroll
        for (int t = 0; t < 2; t++) {
            int id = tid + t * 256;                  // 0..511
            int row = id >> 2, c = id & 3;           // row 0..127, 16B chunk 0..3
            uint32_t dst = base + row * ROWB + c * 16;
            size_t aoff = (size_t)(bm + row) * K + k0 + c * 8;
            size_t boff = (size_t)(bn + row) * K + k0 + c * 8;
            cp_async16(dst,              Ah + aoff);
            cp_async16(dst + TILEB,      Al + aoff);
            cp_async16(dst + 2 * TILEB,  Bh + boff);
            cp_async16(dst + 3 * TILEB,  Bl + boff);
        }
        cp_commit();
    };

    load_stage(0, 0);
    load_stage(1, 1);

    float acc[4][4][4];
    #pragma unroll
    for (int i = 0; i < 4; i++)
        #pragma unroll
        for (int j = 0; j < 4; j++)
            #pragma unroll
            for (int r = 0; r < 4; r++) acc[i][j][r] = 0.f;

    // ldmatrix base addresses (per-lane, stage-relative)
    const int laneA_row = wm * 64 + (lane & 15);           // + mt*16
    const uint32_t laneA_off = laneA_row * ROWB + (lane >> 4) * 16;
    const int l16 = lane & 15;
    const int laneB_row = wn * 32 + (l16 & 7);             // + nt*8
    const uint32_t laneB_off = laneB_row * ROWB + (l16 >> 3) * 16;

    for (int i = 0; i < NK; i++) {
        const int s = i & 1;
        cp_wait<1>();
        __syncthreads();

        const uint32_t base = sb + s * STAGEB;
        #pragma unroll
        for (int kk = 0; kk < 2; kk++) {               // two k16 steps per GBK=32
            const uint32_t kb = kk * 32;               // 16 bf16 = 32 bytes
            uint32_t ah[4][4], al[4][4], bh[4][2], bl[4][2];
            #pragma unroll
            for (int mt = 0; mt < 4; mt++) {
                uint32_t ad = base + laneA_off + mt * (16 * ROWB) + kb;
                ldsm_x4(ah[mt], ad);
                ldsm_x4(al[mt], ad + TILEB);
            }
            #pragma unroll
            for (int nt = 0; nt < 4; nt++) {
                uint32_t bd = base + 2 * TILEB + laneB_off + nt * (8 * ROWB) + kb;
                ldsm_x2(bh[nt], bd);
                ldsm_x2(bl[nt], bd + TILEB);
            }
            #pragma unroll
            for (int mt = 0; mt < 4; mt++)
                #pragma unroll
                for (int nt = 0; nt < 4; nt++)
                    mma_bf16(acc[mt][nt], ah[mt], bh[nt]);
            #pragma unroll
            for (int mt = 0; mt < 4; mt++)
                #pragma unroll
                for (int nt = 0; nt < 4; nt++)
                    mma_bf16(acc[mt][nt], ah[mt], bl[nt]);
            #pragma unroll
            for (int mt = 0; mt < 4; mt++)
                #pragma unroll
                for (int nt = 0; nt < 4; nt++)
                    mma_bf16(acc[mt][nt], al[mt], bh[nt]);
        }
        __syncthreads();
        if (i + 2 < NK) load_stage(s, i + 2);
    }

    // Epilogue: c0,c1 -> (row, col..col+1); c2,c3 -> (row+8, col..col+1)
    #pragma unroll
    for (int mt = 0; mt < 4; mt++) {
        #pragma unroll
        for (int nt = 0; nt < 4; nt++) {
            int row = bm + wm * 64 + mt * 16 + (lane >> 2);
            int col = bn + wn * 32 + nt * 8 + (lane & 3) * 2;
            float b0 = 0.f, b1 = 0.f;
            if (BIAS) { b0 = bias[col]; b1 = bias[col + 1]; }
            float2 v0 = make_float2(acc[mt][nt][0] + b0, acc[mt][nt][1] + b1);
            float2 v1 = make_float2(acc[mt][nt][2] + b0, acc[mt][nt][3] + b1);
            *(float2*)&C[(size_t)row * N + col] = v0;
            *(float2*)&C[(size_t)(row + 8) * N + col] = v1;
        }
    }
}

// ---------------------------------------------------------------------------
// Flash attention (causal), fp32, 64x64 tiles (unchanged from R2 pass).
// ---------------------------------------------------------------------------
#define PAD 68
#define ATTN_SMEM (4 * 64 * PAD * 4)

__global__ void __launch_bounds__(256) attn_kernel(const float* __restrict__ qkv,
                                                   float* __restrict__ ctx)
{
    extern __shared__ float sm[];
    float* Qs  = sm;
    float* KsT = sm + 64 * PAD;
    float* Vs  = sm + 2 * 64 * PAD;
    float* Ps  = sm + 3 * 64 * PAD;

    const int mblk = blockIdx.x;
    const int bh   = blockIdx.y;
    const int b = bh >> 4, h = bh & 15;
    const int tid = threadIdx.x;
    const int tx = tid & 15, ty = tid >> 4;
    const int r0 = ty * 4, c0 = tx * 4;
    const int m0 = mblk * 64;
    const float scale = 0.125f;

    #pragma unroll
    for (int l = 0; l < 4; l++) {
        int idx = tid + l * 256;
        int row = idx >> 4, dc = (idx & 15) << 2;
        float4 v = *(const float4*)&qkv[(size_t)(b * S_LEN + m0 + row) * TRIPLE + h * DHEAD + dc];
        *(float4*)&Qs[row * PAD + dc] = v;
    }

    float acc[4][4];
    float m_i[4], l_i[4];
    #pragma unroll
    for (int i = 0; i < 4; i++) {
        m_i[i] = -1e30f; l_i[i] = 0.f;
        #pragma unroll
        for (int j = 0; j < 4; j++) acc[i][j] = 0.f;
    }

    const int nblocks = mblk + 1;
    for (int nb = 0; nb < nblocks; nb++) {
        const int n0 = nb * 64;
        __syncthreads();
        #pragma unroll
        for (int l = 0; l < 4; l++) {
            int idx = tid + l * 256;
            int c = idx >> 4, dc = (idx & 15) << 2;
            size_t base = (size_t)(b * S_LEN + n0 + c) * TRIPLE + h * DHEAD + dc;
            float4 kv = *(const float4*)&qkv[base + DMODEL];
            KsT[(dc + 0) * PAD + c] = kv.x;
            KsT[(dc + 1) * PAD + c] = kv.y;
            KsT[(dc + 2) * PAD + c] = kv.z;
            KsT[(dc + 3) * PAD + c] = kv.w;
            float4 vv = *(const float4*)&qkv[base + 2 * DMODEL];
            *(float4*)&Vs[c * PAD + dc] = vv;
        }
        __syncthreads();

        float s[4][4];
        #pragma unroll
        for (int i = 0; i < 4; i++)
            #pragma unroll
            for (int j = 0; j < 4; j++) s[i][j] = 0.f;
        #pragma unroll 8
        for (int d = 0; d < 64; d++) {
            float rq0 = Qs[(r0 + 0) * PAD + d];
            float rq1 = Qs[(r0 + 1) * PAD + d];
            float rq2 = Qs[(r0 + 2) * PAD + d];
            float rq3 = Qs[(r0 + 3) * PAD + d];
            float4 rk = *(const float4*)&KsT[d * PAD + c0];
            s[0][0] = fmaf(rq0, rk.x, s[0][0]); s[0][1] = fmaf(rq0, rk.y, s[0][1]);
            s[0][2] = fmaf(rq0, rk.z, s[0][2]); s[0][3] = fmaf(rq0, rk.w, s[0][3]);
            s[1][0] = fmaf(rq1, rk.x, s[1][0]); s[1][1] = fmaf(rq1, rk.y, s[1][1]);
            s[1][2] = fmaf(rq1, rk.z, s[1][2]); s[1][3] = fmaf(rq1, rk.w, s[1][3]);
            s[2][0] = fmaf(rq2, rk.x, s[2][0]); s[2][1] = fmaf(rq2, rk.y, s[2][1]);
            s[2][2] = fmaf(rq2, rk.z, s[2][2]); s[2][3] = fmaf(rq2, rk.w, s[2][3]);
            s[3][0] = fmaf(rq3, rk.x, s[3][0]); s[3][1] = fmaf(rq3, rk.y, s[3][1]);
            s[3][2] = fmaf(rq3, rk.z, s[3][2]); s[3][3] = fmaf(rq3, rk.w, s[3][3]);
        }

        const bool diag = (nb == mblk);
        #pragma unroll
        for (int i = 0; i < 4; i++)
            #pragma unroll
            for (int j = 0; j < 4; j++) {
                s[i][j] *= scale;
                if (diag && (n0 + c0 + j) > (m0 + r0 + i)) s[i][j] = -1e30f;
            }

        float mnew[4], rs[4], alpha[4];
        #pragma unroll
        for (int i = 0; i < 4; i++) {
            float mx = fmaxf(fmaxf(s[i][0], s[i][1]), fmaxf(s[i][2], s[i][3]));
            #pragma unroll
            for (int off = 8; off > 0; off >>= 1)
                mx = fmaxf(mx, __shfl_xor_sync(0xffffffffu, mx, off, 16));
            mnew[i] = mx;
        }
        #pragma unroll
        for (int i = 0; i < 4; i++) {
            float mi2 = fmaxf(m_i[i], mnew[i]);
            alpha[i] = __expf(m_i[i] - mi2);
            m_i[i] = mi2;
            float r = 0.f;
            #pragma unroll
            for (int j = 0; j < 4; j++) {
                float p = __expf(s[i][j] - mi2);
                s[i][j] = p;
                r += p;
            }
            #pragma unroll
            for (int off = 8; off > 0; off >>= 1)
                r += __shfl_xor_sync(0xffffffffu, r, off, 16);
            rs[i] = r;
        }
        #pragma unroll
        for (int i = 0; i < 4; i++) {
            l_i[i] = l_i[i] * alpha[i] + rs[i];
            #pragma unroll
            for (int j = 0; j < 4; j++) acc[i][j] *= alpha[i];
        }

        #pragma unroll
        for (int i = 0; i < 4; i++)
            *(float4*)&Ps[(r0 + i) * PAD + c0] =
                make_float4(s[i][0], s[i][1], s[i][2], s[i][3]);
        __syncthreads();

        #pragma unroll 8
        for (int c = 0; c < 64; c++) {
            float rp0 = Ps[(r0 + 0) * PAD + c];
            float rp1 = Ps[(r0 + 1) * PAD + c];
            float rp2 = Ps[(r0 + 2) * PAD + c];
            float rp3 = Ps[(r0 + 3) * PAD + c];
            float4 rv = *(const float4*)&Vs[c * PAD + c0];
            acc[0][0] = fmaf(rp0, rv.x, acc[0][0]); acc[0][1] = fmaf(rp0, rv.y, acc[0][1]);
            acc[0][2] = fmaf(rp0, rv.z, acc[0][2]); acc[0][3] = fmaf(rp0, rv.w, acc[0][3]);
            acc[1][0] = fmaf(rp1, rv.x, acc[1][0]); acc[1][1] = fmaf(rp1, rv.y, acc[1][1]);
            acc[1][2] = fmaf(rp1, rv.z, acc[1][2]); acc[1][3] = fmaf(rp1, rv.w, acc[1][3]);
            acc[2][0] = fmaf(rp2, rv.x, acc[2][0]); acc[2][1] = fmaf(rp2, rv.y, acc[2][1]);
            acc[2][2] = fmaf(rp2, rv.z, acc[2][2]); acc[2][3] = fmaf(rp2, rv.w, acc[2][3]);
            acc[3][0] = fmaf(rp3, rv.x, acc[3][0]); acc[3][1] = fmaf(rp3, rv.y, acc[3][1]);
            acc[3][2] = fmaf(rp3, rv.z, acc[3][2]); acc[3][3] = fmaf(rp3, rv.w, acc[3][3]);
        }
    }

    #pragma unroll
    for (int i = 0; i < 4; i++) {
        float inv = 1.f / l_i[i];
        float4 o = make_float4(acc[i][0] * inv, acc[i][1] * inv,
                               acc[i][2] * inv, acc[i][3] * inv);
        *(float4*)&ctx[(size_t)(b * S_LEN + m0 + r0 + i) * DMODEL + h * DHEAD + c0] = o;
    }
}

// ---------------------------------------------------------------------------
extern "C" void kernel_launch(void* const* d_in, const int* in_sizes, int n_in,
                              void* d_out, int out_size)
{
    const float* x      = (const float*)d_in[0];  // [2,2048,1024]
    const float* w_qkv  = (const float*)d_in[1];  // [3072,1024]
    const float* w_proj = (const float*)d_in[2];  // [1024,1024]
    const float* b_proj = (const float*)d_in[3];  // [1024]
    float* out = (float*)d_out;                   // [2,2048,1024]

    float *qkv, *ctx;
    cudaGetSymbolAddress((void**)&qkv, g_qkv);
    cudaGetSymbolAddress((void**)&ctx, g_ctx);
    __nv_bfloat16 *xhi, *xlo, *wqh, *wql, *chi, *clo, *wph, *wpl;
    cudaGetSymbolAddress((void**)&xhi, g_xhi);
    cudaGetSymbolAddress((void**)&xlo, g_xlo);
    cudaGetSymbolAddress((void**)&wqh, g_wqh);
    cudaGetSymbolAddress((void**)&wql, g_wql);
    cudaGetSymbolAddress((void**)&chi, g_chi);
    cudaGetSymbolAddress((void**)&clo, g_clo);
    cudaGetSymbolAddress((void**)&wph, g_wph);
    cudaGetSymbolAddress((void**)&wpl, g_wpl);

    cudaFuncSetAttribute(attn_kernel, cudaFuncAttributeMaxDynamicSharedMemorySize, ATTN_SMEM);
    cudaFuncSetAttribute(mma_gemm<false>, cudaFuncAttributeMaxDynamicSharedMemorySize, GEMM_SMEM);
    cudaFuncSetAttribute(mma_gemm<true>,  cudaFuncAttributeMaxDynamicSharedMemorySize, GEMM_SMEM);

    // Split inputs to bf16 hi/lo
    split_fp32<<<(MTOT * DMODEL / 4) / 256, 256>>>(x, xhi, xlo);
    split_fp32<<<(TRIPLE * DMODEL / 4) / 256, 256>>>(w_qkv, wqh, wql);
    split_fp32<<<(DMODEL * DMODEL / 4) / 256, 256>>>(w_proj, wph, wpl);

    // 1) QKV projection on tensor cores (split bf16, fp32 accum)
    {
        dim3 grid(TRIPLE / GBN, MTOT / GBM);
        mma_gemm<false><<<grid, 256, GEMM_SMEM>>>(xhi, xlo, wqh, wql, nullptr, qkv,
                                                  MTOT, TRIPLE, DMODEL);
    }
    // 2) Causal flash attention (fp32)
    {
        dim3 grid(S_LEN / 64, BATCH * NHEAD);
        attn_kernel<<<grid, 256, ATTN_SMEM>>>(qkv, ctx);
    }
    // 3) Output projection on tensor cores (with bias)
    split_fp32<<<(MTOT * DMODEL / 4) / 256, 256>>>(ctx, chi, clo);
    {
        dim3 grid(DMODEL / GBN, MTOT / GBM);
        mma_gemm<true><<<grid, 256, GEMM_SMEM>>>(chi, clo, wph, wpl, b_proj, out,
                                                 MTOT, DMODEL, DMODEL);
    }
}

// round 5
// speedup vs baseline: 2.6687x; 1.7532x over previous
#include <cuda_runtime.h>
#include <cuda_bf16.h>
#include <cstdint>

#define BATCH   2
#define S_LEN   2048
#define DMODEL  1024
#define NHEAD   16
#define DHEAD   64
#define TRIPLE  (3 * DMODEL)    // 3072
#define MTOT    (BATCH * S_LEN) // 4096

// ---------------------------------------------------------------------------
// Scratch (allocation-free: __device__ globals)
// ---------------------------------------------------------------------------
__device__ float g_qkv[(size_t)MTOT * TRIPLE];   // fp32 QKV output
__device__ float g_ctx[(size_t)MTOT * DMODEL];   // fp32 attention output

__device__ __nv_bfloat16 g_xhi[(size_t)MTOT * DMODEL];
__device__ __nv_bfloat16 g_xlo[(size_t)MTOT * DMODEL];
__device__ __nv_bfloat16 g_wqh[(size_t)TRIPLE * DMODEL];
__device__ __nv_bfloat16 g_wql[(size_t)TRIPLE * DMODEL];
__device__ __nv_bfloat16 g_chi[(size_t)MTOT * DMODEL];
__device__ __nv_bfloat16 g_clo[(size_t)MTOT * DMODEL];
__device__ __nv_bfloat16 g_wph[(size_t)DMODEL * DMODEL];
__device__ __nv_bfloat16 g_wpl[(size_t)DMODEL * DMODEL];

// ---------------------------------------------------------------------------
// PTX helpers (Ampere-class: legal on sm_103)
// ---------------------------------------------------------------------------
__device__ __forceinline__ void cp_async16(uint32_t dst, const void* src) {
    asm volatile("cp.async.cg.shared.global [%0], [%1], 16;"
                 :: "r"(dst), "l"(__cvta_generic_to_global(src)));
}
__device__ __forceinline__ void cp_commit() {
    asm volatile("cp.async.commit_group;" ::: "memory");
}
template <int N> __device__ __forceinline__ void cp_wait() {
    asm volatile("cp.async.wait_group %0;" :: "n"(N) : "memory");
}
__device__ __forceinline__ void ldsm_x4(uint32_t* r, uint32_t addr) {
    asm volatile("ldmatrix.sync.aligned.m8n8.x4.shared.b16 {%0,%1,%2,%3}, [%4];"
                 : "=r"(r[0]), "=r"(r[1]), "=r"(r[2]), "=r"(r[3]) : "r"(addr));
}
__device__ __forceinline__ void ldsm_x2(uint32_t* r, uint32_t addr) {
    asm volatile("ldmatrix.sync.aligned.m8n8.x2.shared.b16 {%0,%1}, [%2];"
                 : "=r"(r[0]), "=r"(r[1]) : "r"(addr));
}
__device__ __forceinline__ void ldsm_x2t(uint32_t* r, uint32_t addr) {
    asm volatile("ldmatrix.sync.aligned.m8n8.x2.trans.shared.b16 {%0,%1}, [%2];"
                 : "=r"(r[0]), "=r"(r[1]) : "r"(addr));
}
__device__ __forceinline__ void mma_bf16(float* d, const uint32_t* a, const uint32_t* b) {
    asm volatile("mma.sync.aligned.m16n8k16.row.col.f32.bf16.bf16.f32 "
                 "{%0,%1,%2,%3}, {%4,%5,%6,%7}, {%8,%9}, {%0,%1,%2,%3};"
                 : "+f"(d[0]), "+f"(d[1]), "+f"(d[2]), "+f"(d[3])
                 : "r"(a[0]), "r"(a[1]), "r"(a[2]), "r"(a[3]), "r"(b[0]), "r"(b[1]));
}
__device__ __forceinline__ uint32_t pack_bf2(float a, float b) {
    __nv_bfloat162 t = __float22bfloat162_rn(make_float2(a, b));
    return *(uint32_t*)&t;
}

// ---------------------------------------------------------------------------
// fp32 -> (hi, lo) bf16 split, 4 elems/thread
// ---------------------------------------------------------------------------
__global__ void __launch_bounds__(256) split_fp32(const float* __restrict__ in,
                                                  __nv_bfloat16* __restrict__ hi,
                                                  __nv_bfloat16* __restrict__ lo) {
    int i = blockIdx.x * 256 + threadIdx.x;
    float4 v = ((const float4*)in)[i];
    __nv_bfloat16 h0 = __float2bfloat16(v.x);
    __nv_bfloat16 h1 = __float2bfloat16(v.y);
    __nv_bfloat16 h2 = __float2bfloat16(v.z);
    __nv_bfloat16 h3 = __float2bfloat16(v.w);
    __nv_bfloat16 l0 = __float2bfloat16(v.x - __bfloat162float(h0));
    __nv_bfloat16 l1 = __float2bfloat16(v.y - __bfloat162float(h1));
    __nv_bfloat16 l2 = __float2bfloat16(v.z - __bfloat162float(h2));
    __nv_bfloat16 l3 = __float2bfloat16(v.w - __bfloat162float(h3));
    __nv_bfloat162* H = (__nv_bfloat162*)hi;
    __nv_bfloat162* L = (__nv_bfloat162*)lo;
    H[2 * i]     = __nv_bfloat162(h0, h1);
    H[2 * i + 1] = __nv_bfloat162(h2, h3);
    L[2 * i]     = __nv_bfloat162(l0, l1);
    L[2 * i + 1] = __nv_bfloat162(l2, l3);
}

// ---------------------------------------------------------------------------
// mma.sync split-bf16 GEMM (unchanged from R4): 128x128x32 CTA tile.
// ---------------------------------------------------------------------------
#define GBM 128
#define GBN 128
#define GBK 32
#define ROWB 80
#define TILEB (128 * ROWB)
#define STAGEB (4 * TILEB)
#define GEMM_SMEM (2 * STAGEB)

template <bool BIAS>
__global__ void __launch_bounds__(256)
mma_gemm(const __nv_bfloat16* __restrict__ Ah, const __nv_bfloat16* __restrict__ Al,
         const __nv_bfloat16* __restrict__ Bh, const __nv_bfloat16* __restrict__ Bl,
         const float* __restrict__ bias, float* __restrict__ C,
         int M, int N, int K)
{
    extern __shared__ char smem[];
    const uint32_t sb = (uint32_t)__cvta_generic_to_shared(smem);
    const int tid = threadIdx.x, wid = tid >> 5, lane = tid & 31;
    const int wm = wid >> 2, wn = wid & 3;
    const int bm = blockIdx.y * GBM, bn = blockIdx.x * GBN;
    const int NK = K / GBK;

    auto load_stage = [&](int s, int kc) {
        uint32_t base = sb + s * STAGEB;
        int k0 = kc * GBK;
        #pragma unroll
        for (int t = 0; t < 2; t++) {
            int id = tid + t * 256;
            int row = id >> 2, c = id & 3;
            uint32_t dst = base + row * ROWB + c * 16;
            size_t aoff = (size_t)(bm + row) * K + k0 + c * 8;
            size_t boff = (size_t)(bn + row) * K + k0 + c * 8;
            cp_async16(dst,              Ah + aoff);
            cp_async16(dst + TILEB,      Al + aoff);
            cp_async16(dst + 2 * TILEB,  Bh + boff);
            cp_async16(dst + 3 * TILEB,  Bl + boff);
        }
        cp_commit();
    };

    load_stage(0, 0);
    load_stage(1, 1);

    float acc[4][4][4];
    #pragma unroll
    for (int i = 0; i < 4; i++)
        #pragma unroll
        for (int j = 0; j < 4; j++)
            #pragma unroll
            for (int r = 0; r < 4; r++) acc[i][j][r] = 0.f;

    const int laneA_row = wm * 64 + (lane & 15);
    const uint32_t laneA_off = laneA_row * ROWB + (lane >> 4) * 16;
    const int l16 = lane & 15;
    const int laneB_row = wn * 32 + (l16 & 7);
    const uint32_t laneB_off = laneB_row * ROWB + (l16 >> 3) * 16;

    for (int i = 0; i < NK; i++) {
        const int s = i & 1;
        cp_wait<1>();
        __syncthreads();

        const uint32_t base = sb + s * STAGEB;
        #pragma unroll
        for (int kk = 0; kk < 2; kk++) {
            const uint32_t kb = kk * 32;
            uint32_t ah[4][4], al[4][4], bh[4][2], bl[4][2];
            #pragma unroll
            for (int mt = 0; mt < 4; mt++) {
                uint32_t ad = base + laneA_off + mt * (16 * ROWB) + kb;
                ldsm_x4(ah[mt], ad);
                ldsm_x4(al[mt], ad + TILEB);
            }
            #pragma unroll
            for (int nt = 0; nt < 4; nt++) {
                uint32_t bd = base + 2 * TILEB + laneB_off + nt * (8 * ROWB) + kb;
                ldsm_x2(bh[nt], bd);
                ldsm_x2(bl[nt], bd + TILEB);
            }
            #pragma unroll
            for (int mt = 0; mt < 4; mt++)
                #pragma unroll
                for (int nt = 0; nt < 4; nt++)
                    mma_bf16(acc[mt][nt], ah[mt], bh[nt]);
            #pragma unroll
            for (int mt = 0; mt < 4; mt++)
                #pragma unroll
                for (int nt = 0; nt < 4; nt++)
                    mma_bf16(acc[mt][nt], ah[mt], bl[nt]);
            #pragma unroll
            for (int mt = 0; mt < 4; mt++)
                #pragma unroll
                for (int nt = 0; nt < 4; nt++)
                    mma_bf16(acc[mt][nt], al[mt], bh[nt]);
        }
        __syncthreads();
        if (i + 2 < NK) load_stage(s, i + 2);
    }

    #pragma unroll
    for (int mt = 0; mt < 4; mt++) {
        #pragma unroll
        for (int nt = 0; nt < 4; nt++) {
            int row = bm + wm * 64 + mt * 16 + (lane >> 2);
            int col = bn + wn * 32 + nt * 8 + (lane & 3) * 2;
            float b0 = 0.f, b1 = 0.f;
            if (BIAS) { b0 = bias[col]; b1 = bias[col + 1]; }
            float2 v0 = make_float2(acc[mt][nt][0] + b0, acc[mt][nt][1] + b1);
            float2 v1 = make_float2(acc[mt][nt][2] + b0, acc[mt][nt][3] + b1);
            *(float2*)&C[(size_t)row * N + col] = v0;
            *(float2*)&C[(size_t)(row + 8) * N + col] = v1;
        }
    }
}

// ---------------------------------------------------------------------------
// Flash attention (causal) on mma.sync bf16 with split precision.
// CTA: 64 Q rows for one (b,h). 4 warps; warp w = rows w*16..w*16+15.
// KV tiles of 64. S = QK^T via 3-pass split; P repacked in regs; PV 3-pass.
// smem: Qh,Ql,Kh,Kl,Vh,Vl each [64][72] bf16 (144B rows, ldmatrix-friendly).
// ---------------------------------------------------------------------------
#define AROWP 72
#define AROWBY (AROWP * 2)           // 144 bytes
#define ATILE  (64 * AROWP)          // elements per tile
#define ATTN_SMEM (6 * ATILE * 2)    // 55296 bytes

__global__ void __launch_bounds__(128) attn_mma(const float* __restrict__ qkv,
                                                float* __restrict__ ctx)
{
    extern __shared__ __nv_bfloat16 as[];
    __nv_bfloat16* Qh = as;
    __nv_bfloat16* Ql = as + ATILE;
    __nv_bfloat16* Kh = as + 2 * ATILE;
    __nv_bfloat16* Kl = as + 3 * ATILE;
    __nv_bfloat16* Vh = as + 4 * ATILE;
    __nv_bfloat16* Vl = as + 5 * ATILE;
    const uint32_t sQh = (uint32_t)__cvta_generic_to_shared(Qh);
    const uint32_t sQl = (uint32_t)__cvta_generic_to_shared(Ql);
    const uint32_t sKh = (uint32_t)__cvta_generic_to_shared(Kh);
    const uint32_t sKl = (uint32_t)__cvta_generic_to_shared(Kl);
    const uint32_t sVh = (uint32_t)__cvta_generic_to_shared(Vh);
    const uint32_t sVl = (uint32_t)__cvta_generic_to_shared(Vl);

    const int mblk = blockIdx.x, bh = blockIdx.y;
    const int b = bh >> 4, h = bh & 15;
    const int tid = threadIdx.x, wid = tid >> 5, lane = tid & 31;
    const int l16 = lane & 15;
    const int m0 = mblk * 64;
    const float scale = 0.125f;

    // Load + split Q tile once
    #pragma unroll
    for (int l = 0; l < 8; l++) {
        int id = tid + l * 128;              // 0..1023
        int row = id >> 4, c4 = (id & 15) << 2;
        float4 v = *(const float4*)&qkv[(size_t)(b * S_LEN + m0 + row) * TRIPLE + h * DHEAD + c4];
        float h0 = __bfloat162float(__float2bfloat16(v.x));
        float h1 = __bfloat162float(__float2bfloat16(v.y));
        float h2 = __bfloat162float(__float2bfloat16(v.z));
        float h3 = __bfloat162float(__float2bfloat16(v.w));
        int off = row * AROWP + c4;
        *(__nv_bfloat162*)&Qh[off]     = __floats2bfloat162_rn(h0, h1);
        *(__nv_bfloat162*)&Qh[off + 2] = __floats2bfloat162_rn(h2, h3);
        *(__nv_bfloat162*)&Ql[off]     = __floats2bfloat162_rn(v.x - h0, v.y - h1);
        *(__nv_bfloat162*)&Ql[off + 2] = __floats2bfloat162_rn(v.z - h2, v.w - h3);
    }

    float o[8][4];
    #pragma unroll
    for (int t = 0; t < 8; t++)
        #pragma unroll
        for (int r = 0; r < 4; r++) o[t][r] = 0.f;
    float m_i[2] = {-1e30f, -1e30f}, l_i[2] = {0.f, 0.f};

    const int row_lo = m0 + wid * 16 + (lane >> 2);   // global Q row of c0/c1
    const int col_in = (lane & 3) * 2;                // col offset within n8 tile

    for (int nb = 0; nb <= mblk; nb++) {
        const int n0 = nb * 64;
        __syncthreads();   // prior iter's K/V reads done; Q stores visible on iter 0

        // Load + split K, V tiles
        #pragma unroll
        for (int l = 0; l < 8; l++) {
            int id = tid + l * 128;
            int row = id >> 4, c4 = (id & 15) << 2;
            size_t base = (size_t)(b * S_LEN + n0 + row) * TRIPLE + h * DHEAD + c4;
            int off = row * AROWP + c4;
            float4 kv = *(const float4*)&qkv[base + DMODEL];
            float kh0 = __bfloat162float(__float2bfloat16(kv.x));
            float kh1 = __bfloat162float(__float2bfloat16(kv.y));
            float kh2 = __bfloat162float(__float2bfloat16(kv.z));
            float kh3 = __bfloat162float(__float2bfloat16(kv.w));
            *(__nv_bfloat162*)&Kh[off]     = __floats2bfloat162_rn(kh0, kh1);
            *(__nv_bfloat162*)&Kh[off + 2] = __floats2bfloat162_rn(kh2, kh3);
            *(__nv_bfloat162*)&Kl[off]     = __floats2bfloat162_rn(kv.x - kh0, kv.y - kh1);
            *(__nv_bfloat162*)&Kl[off + 2] = __floats2bfloat162_rn(kv.z - kh2, kv.w - kh3);
            float4 vv = *(const float4*)&qkv[base + 2 * DMODEL];
            float vh0 = __bfloat162float(__float2bfloat16(vv.x));
            float vh1 = __bfloat162float(__float2bfloat16(vv.y));
            float vh2 = __bfloat162float(__float2bfloat16(vv.z));
            float vh3 = __bfloat162float(__float2bfloat16(vv.w));
            *(__nv_bfloat162*)&Vh[off]     = __floats2bfloat162_rn(vh0, vh1);
            *(__nv_bfloat162*)&Vh[off + 2] = __floats2bfloat162_rn(vh2, vh3);
            *(__nv_bfloat162*)&Vl[off]     = __floats2bfloat162_rn(vv.x - vh0, vv.y - vh1);
            *(__nv_bfloat162*)&Vl[off + 2] = __floats2bfloat162_rn(vv.z - vh2, vv.w - vh3);
        }
        __syncthreads();

        // ---- S = Q K^T (split, 3 passes), accumulate fp32 ----
        float s[8][4];
        #pragma unroll
        for (int t = 0; t < 8; t++)
            #pragma unroll
            for (int r = 0; r < 4; r++) s[t][r] = 0.f;

        #pragma unroll
        for (int kk = 0; kk < 4; kk++) {
            uint32_t qh4[4], ql4[4];
            uint32_t qaddr = (wid * 16 + (lane & 15)) * AROWBY + (lane >> 4) * 16 + kk * 32;
            ldsm_x4(qh4, sQh + qaddr);
            ldsm_x4(ql4, sQl + qaddr);
            #pragma unroll
            for (int t = 0; t < 8; t++) {
                uint32_t kaddr = (t * 8 + (l16 & 7)) * AROWBY + (l16 >> 3) * 16 + kk * 32;
                uint32_t kh2r[2], kl2r[2];
                ldsm_x2(kh2r, sKh + kaddr);
                ldsm_x2(kl2r, sKl + kaddr);
                mma_bf16(s[t], qh4, kh2r);
                mma_bf16(s[t], qh4, kl2r);
                mma_bf16(s[t], ql4, kh2r);
            }
        }

        // ---- scale + causal mask (diag tile only) ----
        if (nb == mblk) {
            #pragma unroll
            for (int t = 0; t < 8; t++) {
                int c0g = n0 + t * 8 + col_in;
                s[t][0] = (c0g     > row_lo)     ? -1e30f : s[t][0] * scale;
                s[t][1] = (c0g + 1 > row_lo)     ? -1e30f : s[t][1] * scale;
                s[t][2] = (c0g     > row_lo + 8) ? -1e30f : s[t][2] * scale;
                s[t][3] = (c0g + 1 > row_lo + 8) ? -1e30f : s[t][3] * scale;
            }
        } else {
            #pragma unroll
            for (int t = 0; t < 8; t++)
                #pragma unroll
                for (int r = 0; r < 4; r++) s[t][r] *= scale;
        }

        // ---- online softmax (2 rows/thread; quad shfl reduce) ----
        float mx0 = -1e30f, mx1 = -1e30f;
        #pragma unroll
        for (int t = 0; t < 8; t++) {
            mx0 = fmaxf(mx0, fmaxf(s[t][0], s[t][1]));
            mx1 = fmaxf(mx1, fmaxf(s[t][2], s[t][3]));
        }
        #pragma unroll
        for (int off = 1; off <= 2; off <<= 1) {
            mx0 = fmaxf(mx0, __shfl_xor_sync(0xffffffffu, mx0, off));
            mx1 = fmaxf(mx1, __shfl_xor_sync(0xffffffffu, mx1, off));
        }
        float mn0 = fmaxf(m_i[0], mx0), mn1 = fmaxf(m_i[1], mx1);
        float al0 = __expf(m_i[0] - mn0), al1 = __expf(m_i[1] - mn1);
        m_i[0] = mn0; m_i[1] = mn1;

        float sum0 = 0.f, sum1 = 0.f;
        #pragma unroll
        for (int t = 0; t < 8; t++) {
            s[t][0] = __expf(s[t][0] - mn0);
            s[t][1] = __expf(s[t][1] - mn0);
            s[t][2] = __expf(s[t][2] - mn1);
            s[t][3] = __expf(s[t][3] - mn1);
            sum0 += s[t][0] + s[t][1];
            sum1 += s[t][2] + s[t][3];
        }
        #pragma unroll
        for (int off = 1; off <= 2; off <<= 1) {
            sum0 += __shfl_xor_sync(0xffffffffu, sum0, off);
            sum1 += __shfl_xor_sync(0xffffffffu, sum1, off);
        }
        l_i[0] = l_i[0] * al0 + sum0;
        l_i[1] = l_i[1] * al1 + sum1;
        #pragma unroll
        for (int t = 0; t < 8; t++) {
            o[t][0] *= al0; o[t][1] *= al0;
            o[t][2] *= al1; o[t][3] *= al1;
        }

        // ---- o += P V (split, 3 passes). P repacked from s in registers. ----
        #pragma unroll
        for (int kk = 0; kk < 4; kk++) {
            const int ta = 2 * kk, tb = 2 * kk + 1;
            uint32_t ph[4], pl[4];
            ph[0] = pack_bf2(s[ta][0], s[ta][1]);
            ph[1] = pack_bf2(s[ta][2], s[ta][3]);
            ph[2] = pack_bf2(s[tb][0], s[tb][1]);
            ph[3] = pack_bf2(s[tb][2], s[tb][3]);
            {
                __nv_bfloat162 h0 = *(__nv_bfloat162*)&ph[0];
                __nv_bfloat162 h1 = *(__nv_bfloat162*)&ph[1];
                __nv_bfloat162 h2 = *(__nv_bfloat162*)&ph[2];
                __nv_bfloat162 h3 = *(__nv_bfloat162*)&ph[3];
                pl[0] = pack_bf2(s[ta][0] - __bfloat162float(h0.x), s[ta][1] - __bfloat162float(h0.y));
                pl[1] = pack_bf2(s[ta][2] - __bfloat162float(h1.x), s[ta][3] - __bfloat162float(h1.y));
                pl[2] = pack_bf2(s[tb][0] - __bfloat162float(h2.x), s[tb][1] - __bfloat162float(h2.y));
                pl[3] = pack_bf2(s[tb][2] - __bfloat162float(h3.x), s[tb][3] - __bfloat162float(h3.y));
            }
            #pragma unroll
            for (int t = 0; t < 8; t++) {
                uint32_t vaddr = (kk * 16 + l16) * AROWBY + t * 16;
                uint32_t vh2r[2], vl2r[2];
                ldsm_x2t(vh2r, sVh + vaddr);
                ldsm_x2t(vl2r, sVl + vaddr);
                mma_bf16(o[t], ph, vh2r);
                mma_bf16(o[t], ph, vl2r);
                mma_bf16(o[t], pl, vh2r);
            }
        }
    }

    // ---- write ctx, normalized ----
    float inv0 = 1.f / l_i[0], inv1 = 1.f / l_i[1];
    #pragma unroll
    for (int t = 0; t < 8; t++) {
        int col = h * DHEAD + t * 8 + col_in;
        *(float2*)&ctx[(size_t)(b * S_LEN + row_lo) * DMODEL + col] =
            make_float2(o[t][0] * inv0, o[t][1] * inv0);
        *(float2*)&ctx[(size_t)(b * S_LEN + row_lo + 8) * DMODEL + col] =
            make_float2(o[t][2] * inv1, o[t][3] * inv1);
    }
}

// ---------------------------------------------------------------------------
extern "C" void kernel_launch(void* const* d_in, const int* in_sizes, int n_in,
                              void* d_out, int out_size)
{
    const float* x      = (const float*)d_in[0];  // [2,2048,1024]
    const float* w_qkv  = (const float*)d_in[1];  // [3072,1024]
    const float* w_proj = (const float*)d_in[2];  // [1024,1024]
    const float* b_proj = (const float*)d_in[3];  // [1024]
    float* out = (float*)d_out;                   // [2,2048,1024]

    float *qkv, *ctx;
    cudaGetSymbolAddress((void**)&qkv, g_qkv);
    cudaGetSymbolAddress((void**)&ctx, g_ctx);
    __nv_bfloat16 *xhi, *xlo, *wqh, *wql, *chi, *clo, *wph, *wpl;
    cudaGetSymbolAddress((void**)&xhi, g_xhi);
    cudaGetSymbolAddress((void**)&xlo, g_xlo);
    cudaGetSymbolAddress((void**)&wqh, g_wqh);
    cudaGetSymbolAddress((void**)&wql, g_wql);
    cudaGetSymbolAddress((void**)&chi, g_chi);
    cudaGetSymbolAddress((void**)&clo, g_clo);
    cudaGetSymbolAddress((void**)&wph, g_wph);
    cudaGetSymbolAddress((void**)&wpl, g_wpl);

    cudaFuncSetAttribute(attn_mma, cudaFuncAttributeMaxDynamicSharedMemorySize, ATTN_SMEM);
    cudaFuncSetAttribute(mma_gemm<false>, cudaFuncAttributeMaxDynamicSharedMemorySize, GEMM_SMEM);
    cudaFuncSetAttribute(mma_gemm<true>,  cudaFuncAttributeMaxDynamicSharedMemorySize, GEMM_SMEM);

    // Split inputs to bf16 hi/lo
    split_fp32<<<(MTOT * DMODEL / 4) / 256, 256>>>(x, xhi, xlo);
    split_fp32<<<(TRIPLE * DMODEL / 4) / 256, 256>>>(w_qkv, wqh, wql);
    split_fp32<<<(DMODEL * DMODEL / 4) / 256, 256>>>(w_proj, wph, wpl);

    // 1) QKV projection (tensor cores, split bf16)
    {
        dim3 grid(TRIPLE / GBN, MTOT / GBM);
        mma_gemm<false><<<grid, 256, GEMM_SMEM>>>(xhi, xlo, wqh, wql, nullptr, qkv,
                                                  MTOT, TRIPLE, DMODEL);
    }
    // 2) Causal flash attention (tensor cores, split bf16)
    {
        dim3 grid(S_LEN / 64, BATCH * NHEAD);
        attn_mma<<<grid, 128, ATTN_SMEM>>>(qkv, ctx);
    }
    // 3) Output projection (tensor cores, split bf16, bias)
    split_fp32<<<(MTOT * DMODEL / 4) / 256, 256>>>(ctx, chi, clo);
    {
        dim3 grid(DMODEL / GBN, MTOT / GBM);
        mma_gemm<true><<<grid, 256, GEMM_SMEM>>>(chi, clo, wph, wpl, b_proj, out,
                                                 MTOT, DMODEL, DMODEL);
    }
}

// round 6
// speedup vs baseline: 2.9089x; 1.0900x over previous
#include <cuda_runtime.h>
#include <cuda_bf16.h>
#include <cstdint>

#define BATCH   2
#define S_LEN   2048
#define DMODEL  1024
#define NHEAD   16
#define DHEAD   64
#define TRIPLE  (3 * DMODEL)    // 3072
#define MTOT    (BATCH * S_LEN) // 4096

// ---------------------------------------------------------------------------
// Scratch (allocation-free: __device__ globals)
// ---------------------------------------------------------------------------
__device__ float g_qkv[(size_t)MTOT * TRIPLE];   // fp32 QKV output
__device__ float g_ctx[(size_t)MTOT * DMODEL];   // fp32 attention output

__device__ __nv_bfloat16 g_xhi[(size_t)MTOT * DMODEL];
__device__ __nv_bfloat16 g_xlo[(size_t)MTOT * DMODEL];
__device__ __nv_bfloat16 g_wqh[(size_t)TRIPLE * DMODEL];
__device__ __nv_bfloat16 g_wql[(size_t)TRIPLE * DMODEL];
__device__ __nv_bfloat16 g_chi[(size_t)MTOT * DMODEL];
__device__ __nv_bfloat16 g_clo[(size_t)MTOT * DMODEL];
__device__ __nv_bfloat16 g_wph[(size_t)DMODEL * DMODEL];
__device__ __nv_bfloat16 g_wpl[(size_t)DMODEL * DMODEL];

// ---------------------------------------------------------------------------
// PTX helpers (Ampere-class: legal on sm_103)
// ---------------------------------------------------------------------------
__device__ __forceinline__ void cp_async16(uint32_t dst, const void* src) {
    asm volatile("cp.async.cg.shared.global [%0], [%1], 16;"
                 :: "r"(dst), "l"(__cvta_generic_to_global(src)));
}
__device__ __forceinline__ void cp_commit() {
    asm volatile("cp.async.commit_group;" ::: "memory");
}
template <int N> __device__ __forceinline__ void cp_wait() {
    asm volatile("cp.async.wait_group %0;" :: "n"(N) : "memory");
}
__device__ __forceinline__ void ldsm_x4(uint32_t* r, uint32_t addr) {
    asm volatile("ldmatrix.sync.aligned.m8n8.x4.shared.b16 {%0,%1,%2,%3}, [%4];"
                 : "=r"(r[0]), "=r"(r[1]), "=r"(r[2]), "=r"(r[3]) : "r"(addr));
}
__device__ __forceinline__ void ldsm_x2(uint32_t* r, uint32_t addr) {
    asm volatile("ldmatrix.sync.aligned.m8n8.x2.shared.b16 {%0,%1}, [%2];"
                 : "=r"(r[0]), "=r"(r[1]) : "r"(addr));
}
__device__ __forceinline__ void ldsm_x2t(uint32_t* r, uint32_t addr) {
    asm volatile("ldmatrix.sync.aligned.m8n8.x2.trans.shared.b16 {%0,%1}, [%2];"
                 : "=r"(r[0]), "=r"(r[1]) : "r"(addr));
}
__device__ __forceinline__ void mma_bf16(float* d, const uint32_t* a, const uint32_t* b) {
    asm volatile("mma.sync.aligned.m16n8k16.row.col.f32.bf16.bf16.f32 "
                 "{%0,%1,%2,%3}, {%4,%5,%6,%7}, {%8,%9}, {%0,%1,%2,%3};"
                 : "+f"(d[0]), "+f"(d[1]), "+f"(d[2]), "+f"(d[3])
                 : "r"(a[0]), "r"(a[1]), "r"(a[2]), "r"(a[3]), "r"(b[0]), "r"(b[1]));
}
__device__ __forceinline__ uint32_t pack_bf2(float a, float b) {
    __nv_bfloat162 t = __float22bfloat162_rn(make_float2(a, b));
    return *(uint32_t*)&t;
}

// ---------------------------------------------------------------------------
// fp32 -> (hi, lo) bf16 split, 4 elems/thread
// ---------------------------------------------------------------------------
__global__ void __launch_bounds__(256) split_fp32(const float* __restrict__ in,
                                                  __nv_bfloat16* __restrict__ hi,
                                                  __nv_bfloat16* __restrict__ lo) {
    int i = blockIdx.x * 256 + threadIdx.x;
    float4 v = ((const float4*)in)[i];
    __nv_bfloat16 h0 = __float2bfloat16(v.x);
    __nv_bfloat16 h1 = __float2bfloat16(v.y);
    __nv_bfloat16 h2 = __float2bfloat16(v.z);
    __nv_bfloat16 h3 = __float2bfloat16(v.w);
    __nv_bfloat16 l0 = __float2bfloat16(v.x - __bfloat162float(h0));
    __nv_bfloat16 l1 = __float2bfloat16(v.y - __bfloat162float(h1));
    __nv_bfloat16 l2 = __float2bfloat16(v.z - __bfloat162float(h2));
    __nv_bfloat16 l3 = __float2bfloat16(v.w - __bfloat162float(h3));
    __nv_bfloat162* H = (__nv_bfloat162*)hi;
    __nv_bfloat162* L = (__nv_bfloat162*)lo;
    H[2 * i]     = __nv_bfloat162(h0, h1);
    H[2 * i + 1] = __nv_bfloat162(h2, h3);
    L[2 * i]     = __nv_bfloat162(l0, l1);
    L[2 * i + 1] = __nv_bfloat162(l2, l3);
}

// ---------------------------------------------------------------------------
// mma.sync split-bf16 GEMM: 128x128x32 CTA tile, now 2 CTAs/SM (reg cap 128).
// ---------------------------------------------------------------------------
#define GBM 128
#define GBN 128
#define GBK 32
#define ROWB 80
#define TILEB (128 * ROWB)
#define STAGEB (4 * TILEB)
#define GEMM_SMEM (2 * STAGEB)

template <bool BIAS>
__global__ void __launch_bounds__(256, 2)
mma_gemm(const __nv_bfloat16* __restrict__ Ah, const __nv_bfloat16* __restrict__ Al,
         const __nv_bfloat16* __restrict__ Bh, const __nv_bfloat16* __restrict__ Bl,
         const float* __restrict__ bias, float* __restrict__ C,
         int M, int N, int K)
{
    extern __shared__ char smem[];
    const uint32_t sb = (uint32_t)__cvta_generic_to_shared(smem);
    const int tid = threadIdx.x, wid = tid >> 5, lane = tid & 31;
    const int wm = wid >> 2, wn = wid & 3;
    const int bm = blockIdx.y * GBM, bn = blockIdx.x * GBN;
    const int NK = K / GBK;

    auto load_stage = [&](int s, int kc) {
        uint32_t base = sb + s * STAGEB;
        int k0 = kc * GBK;
        #pragma unroll
        for (int t = 0; t < 2; t++) {
            int id = tid + t * 256;
            int row = id >> 2, c = id & 3;
            uint32_t dst = base + row * ROWB + c * 16;
            size_t aoff = (size_t)(bm + row) * K + k0 + c * 8;
            size_t boff = (size_t)(bn + row) * K + k0 + c * 8;
            cp_async16(dst,              Ah + aoff);
            cp_async16(dst + TILEB,      Al + aoff);
            cp_async16(dst + 2 * TILEB,  Bh + boff);
            cp_async16(dst + 3 * TILEB,  Bl + boff);
        }
        cp_commit();
    };

    load_stage(0, 0);
    load_stage(1, 1);

    float acc[4][4][4];
    #pragma unroll
    for (int i = 0; i < 4; i++)
        #pragma unroll
        for (int j = 0; j < 4; j++)
            #pragma unroll
            for (int r = 0; r < 4; r++) acc[i][j][r] = 0.f;

    const int laneA_row = wm * 64 + (lane & 15);
    const uint32_t laneA_off = laneA_row * ROWB + (lane >> 4) * 16;
    const int l16 = lane & 15;
    const int laneB_row = wn * 32 + (l16 & 7);
    const uint32_t laneB_off = laneB_row * ROWB + (l16 >> 3) * 16;

    for (int i = 0; i < NK; i++) {
        const int s = i & 1;
        cp_wait<1>();
        __syncthreads();

        const uint32_t base = sb + s * STAGEB;
        #pragma unroll
        for (int kk = 0; kk < 2; kk++) {
            const uint32_t kb = kk * 32;
            uint32_t ah[4][4], al[4][4], bh[4][2], bl[4][2];
            #pragma unroll
            for (int mt = 0; mt < 4; mt++) {
                uint32_t ad = base + laneA_off + mt * (16 * ROWB) + kb;
                ldsm_x4(ah[mt], ad);
                ldsm_x4(al[mt], ad + TILEB);
            }
            #pragma unroll
            for (int nt = 0; nt < 4; nt++) {
                uint32_t bd = base + 2 * TILEB + laneB_off + nt * (8 * ROWB) + kb;
                ldsm_x2(bh[nt], bd);
                ldsm_x2(bl[nt], bd + TILEB);
            }
            #pragma unroll
            for (int mt = 0; mt < 4; mt++)
                #pragma unroll
                for (int nt = 0; nt < 4; nt++)
                    mma_bf16(acc[mt][nt], ah[mt], bh[nt]);
            #pragma unroll
            for (int mt = 0; mt < 4; mt++)
                #pragma unroll
                for (int nt = 0; nt < 4; nt++)
                    mma_bf16(acc[mt][nt], ah[mt], bl[nt]);
            #pragma unroll
            for (int mt = 0; mt < 4; mt++)
                #pragma unroll
                for (int nt = 0; nt < 4; nt++)
                    mma_bf16(acc[mt][nt], al[mt], bh[nt]);
        }
        __syncthreads();
        if (i + 2 < NK) load_stage(s, i + 2);
    }

    #pragma unroll
    for (int mt = 0; mt < 4; mt++) {
        #pragma unroll
        for (int nt = 0; nt < 4; nt++) {
            int row = bm + wm * 64 + mt * 16 + (lane >> 2);
            int col = bn + wn * 32 + nt * 8 + (lane & 3) * 2;
            float b0 = 0.f, b1 = 0.f;
            if (BIAS) { b0 = bias[col]; b1 = bias[col + 1]; }
            float2 v0 = make_float2(acc[mt][nt][0] + b0, acc[mt][nt][1] + b1);
            float2 v1 = make_float2(acc[mt][nt][2] + b0, acc[mt][nt][3] + b1);
            *(float2*)&C[(size_t)row * N + col] = v0;
            *(float2*)&C[(size_t)(row + 8) * N + col] = v1;
        }
    }
}

// ---------------------------------------------------------------------------
// Flash attention (causal) on mma.sync bf16 with split precision (as R5).
// ---------------------------------------------------------------------------
#define AROWP 72
#define AROWBY (AROWP * 2)           // 144 bytes
#define ATILE  (64 * AROWP)
#define ATTN_SMEM (6 * ATILE * 2)    // 55296 bytes

__global__ void __launch_bounds__(128) attn_mma(const float* __restrict__ qkv,
                                                float* __restrict__ ctx)
{
    extern __shared__ __nv_bfloat16 as[];
    __nv_bfloat16* Qh = as;
    __nv_bfloat16* Ql = as + ATILE;
    __nv_bfloat16* Kh = as + 2 * ATILE;
    __nv_bfloat16* Kl = as + 3 * ATILE;
    __nv_bfloat16* Vh = as + 4 * ATILE;
    __nv_bfloat16* Vl = as + 5 * ATILE;
    const uint32_t sQh = (uint32_t)__cvta_generic_to_shared(Qh);
    const uint32_t sQl = (uint32_t)__cvta_generic_to_shared(Ql);
    const uint32_t sKh = (uint32_t)__cvta_generic_to_shared(Kh);
    const uint32_t sKl = (uint32_t)__cvta_generic_to_shared(Kl);
    const uint32_t sVh = (uint32_t)__cvta_generic_to_shared(Vh);
    const uint32_t sVl = (uint32_t)__cvta_generic_to_shared(Vl);

    const int mblk = blockIdx.x, bh = blockIdx.y;
    const int b = bh >> 4, h = bh & 15;
    const int tid = threadIdx.x, wid = tid >> 5, lane = tid & 31;
    const int l16 = lane & 15;
    const int m0 = mblk * 64;
    const float scale = 0.125f;

    #pragma unroll
    for (int l = 0; l < 8; l++) {
        int id = tid + l * 128;
        int row = id >> 4, c4 = (id & 15) << 2;
        float4 v = *(const float4*)&qkv[(size_t)(b * S_LEN + m0 + row) * TRIPLE + h * DHEAD + c4];
        float h0 = __bfloat162float(__float2bfloat16(v.x));
        float h1 = __bfloat162float(__float2bfloat16(v.y));
        float h2 = __bfloat162float(__float2bfloat16(v.z));
        float h3 = __bfloat162float(__float2bfloat16(v.w));
        int off = row * AROWP + c4;
        *(__nv_bfloat162*)&Qh[off]     = __floats2bfloat162_rn(h0, h1);
        *(__nv_bfloat162*)&Qh[off + 2] = __floats2bfloat162_rn(h2, h3);
        *(__nv_bfloat162*)&Ql[off]     = __floats2bfloat162_rn(v.x - h0, v.y - h1);
        *(__nv_bfloat162*)&Ql[off + 2] = __floats2bfloat162_rn(v.z - h2, v.w - h3);
    }

    float o[8][4];
    #pragma unroll
    for (int t = 0; t < 8; t++)
        #pragma unroll
        for (int r = 0; r < 4; r++) o[t][r] = 0.f;
    float m_i[2] = {-1e30f, -1e30f}, l_i[2] = {0.f, 0.f};

    const int row_lo = m0 + wid * 16 + (lane >> 2);
    const int col_in = (lane & 3) * 2;

    for (int nb = 0; nb <= mblk; nb++) {
        const int n0 = nb * 64;
        __syncthreads();

        #pragma unroll
        for (int l = 0; l < 8; l++) {
            int id = tid + l * 128;
            int row = id >> 4, c4 = (id & 15) << 2;
            size_t base = (size_t)(b * S_LEN + n0 + row) * TRIPLE + h * DHEAD + c4;
            int off = row * AROWP + c4;
            float4 kv = *(const float4*)&qkv[base + DMODEL];
            float kh0 = __bfloat162float(__float2bfloat16(kv.x));
            float kh1 = __bfloat162float(__float2bfloat16(kv.y));
            float kh2 = __bfloat162float(__float2bfloat16(kv.z));
            float kh3 = __bfloat162float(__float2bfloat16(kv.w));
            *(__nv_bfloat162*)&Kh[off]     = __floats2bfloat162_rn(kh0, kh1);
            *(__nv_bfloat162*)&Kh[off + 2] = __floats2bfloat162_rn(kh2, kh3);
            *(__nv_bfloat162*)&Kl[off]     = __floats2bfloat162_rn(kv.x - kh0, kv.y - kh1);
            *(__nv_bfloat162*)&Kl[off + 2] = __floats2bfloat162_rn(kv.z - kh2, kv.w - kh3);
            float4 vv = *(const float4*)&qkv[base + 2 * DMODEL];
            float vh0 = __bfloat162float(__float2bfloat16(vv.x));
            float vh1 = __bfloat162float(__float2bfloat16(vv.y));
            float vh2 = __bfloat162float(__float2bfloat16(vv.z));
            float vh3 = __bfloat162float(__float2bfloat16(vv.w));
            *(__nv_bfloat162*)&Vh[off]     = __floats2bfloat162_rn(vh0, vh1);
            *(__nv_bfloat162*)&Vh[off + 2] = __floats2bfloat162_rn(vh2, vh3);
            *(__nv_bfloat162*)&Vl[off]     = __floats2bfloat162_rn(vv.x - vh0, vv.y - vh1);
            *(__nv_bfloat162*)&Vl[off + 2] = __floats2bfloat162_rn(vv.z - vh2, vv.w - vh3);
        }
        __syncthreads();

        float s[8][4];
        #pragma unroll
        for (int t = 0; t < 8; t++)
            #pragma unroll
            for (int r = 0; r < 4; r++) s[t][r] = 0.f;

        #pragma unroll
        for (int kk = 0; kk < 4; kk++) {
            uint32_t qh4[4], ql4[4];
            uint32_t qaddr = (wid * 16 + (lane & 15)) * AROWBY + (lane >> 4) * 16 + kk * 32;
            ldsm_x4(qh4, sQh + qaddr);
            ldsm_x4(ql4, sQl + qaddr);
            #pragma unroll
            for (int t = 0; t < 8; t++) {
                uint32_t kaddr = (t * 8 + (l16 & 7)) * AROWBY + (l16 >> 3) * 16 + kk * 32;
                uint32_t kh2r[2], kl2r[2];
                ldsm_x2(kh2r, sKh + kaddr);
                ldsm_x2(kl2r, sKl + kaddr);
                mma_bf16(s[t], qh4, kh2r);
                mma_bf16(s[t], qh4, kl2r);
                mma_bf16(s[t], ql4, kh2r);
            }
        }

        if (nb == mblk) {
            #pragma unroll
            for (int t = 0; t < 8; t++) {
                int c0g = n0 + t * 8 + col_in;
                s[t][0] = (c0g     > row_lo)     ? -1e30f : s[t][0] * scale;
                s[t][1] = (c0g + 1 > row_lo)     ? -1e30f : s[t][1] * scale;
                s[t][2] = (c0g     > row_lo + 8) ? -1e30f : s[t][2] * scale;
                s[t][3] = (c0g + 1 > row_lo + 8) ? -1e30f : s[t][3] * scale;
            }
        } else {
            #pragma unroll
            for (int t = 0; t < 8; t++)
                #pragma unroll
                for (int r = 0; r < 4; r++) s[t][r] *= scale;
        }

        float mx0 = -1e30f, mx1 = -1e30f;
        #pragma unroll
        for (int t = 0; t < 8; t++) {
            mx0 = fmaxf(mx0, fmaxf(s[t][0], s[t][1]));
            mx1 = fmaxf(mx1, fmaxf(s[t][2], s[t][3]));
        }
        #pragma unroll
        for (int off = 1; off <= 2; off <<= 1) {
            mx0 = fmaxf(mx0, __shfl_xor_sync(0xffffffffu, mx0, off));
            mx1 = fmaxf(mx1, __shfl_xor_sync(0xffffffffu, mx1, off));
        }
        float mn0 = fmaxf(m_i[0], mx0), mn1 = fmaxf(m_i[1], mx1);
        float al0 = __expf(m_i[0] - mn0), al1 = __expf(m_i[1] - mn1);
        m_i[0] = mn0; m_i[1] = mn1;

        float sum0 = 0.f, sum1 = 0.f;
        #pragma unroll
        for (int t = 0; t < 8; t++) {
            s[t][0] = __expf(s[t][0] - mn0);
            s[t][1] = __expf(s[t][1] - mn0);
            s[t][2] = __expf(s[t][2] - mn1);
            s[t][3] = __expf(s[t][3] - mn1);
            sum0 += s[t][0] + s[t][1];
            sum1 += s[t][2] + s[t][3];
        }
        #pragma unroll
        for (int off = 1; off <= 2; off <<= 1) {
            sum0 += __shfl_xor_sync(0xffffffffu, sum0, off);
            sum1 += __shfl_xor_sync(0xffffffffu, sum1, off);
        }
        l_i[0] = l_i[0] * al0 + sum0;
        l_i[1] = l_i[1] * al1 + sum1;
        #pragma unroll
        for (int t = 0; t < 8; t++) {
            o[t][0] *= al0; o[t][1] *= al0;
            o[t][2] *= al1; o[t][3] *= al1;
        }

        #pragma unroll
        for (int kk = 0; kk < 4; kk++) {
            const int ta = 2 * kk, tb = 2 * kk + 1;
            uint32_t ph[4], pl[4];
            ph[0] = pack_bf2(s[ta][0], s[ta][1]);
            ph[1] = pack_bf2(s[ta][2], s[ta][3]);
            ph[2] = pack_bf2(s[tb][0], s[tb][1]);
            ph[3] = pack_bf2(s[tb][2], s[tb][3]);
            {
                __nv_bfloat162 h0 = *(__nv_bfloat162*)&ph[0];
                __nv_bfloat162 h1 = *(__nv_bfloat162*)&ph[1];
                __nv_bfloat162 h2 = *(__nv_bfloat162*)&ph[2];
                __nv_bfloat162 h3 = *(__nv_bfloat162*)&ph[3];
                pl[0] = pack_bf2(s[ta][0] - __bfloat162float(h0.x), s[ta][1] - __bfloat162float(h0.y));
                pl[1] = pack_bf2(s[ta][2] - __bfloat162float(h1.x), s[ta][3] - __bfloat162float(h1.y));
                pl[2] = pack_bf2(s[tb][0] - __bfloat162float(h2.x), s[tb][1] - __bfloat162float(h2.y));
                pl[3] = pack_bf2(s[tb][2] - __bfloat162float(h3.x), s[tb][3] - __bfloat162float(h3.y));
            }
            #pragma unroll
            for (int t = 0; t < 8; t++) {
                uint32_t vaddr = (kk * 16 + l16) * AROWBY + t * 16;
                uint32_t vh2r[2], vl2r[2];
                ldsm_x2t(vh2r, sVh + vaddr);
                ldsm_x2t(vl2r, sVl + vaddr);
                mma_bf16(o[t], ph, vh2r);
                mma_bf16(o[t], ph, vl2r);
                mma_bf16(o[t], pl, vh2r);
            }
        }
    }

    float inv0 = 1.f / l_i[0], inv1 = 1.f / l_i[1];
    #pragma unroll
    for (int t = 0; t < 8; t++) {
        int col = h * DHEAD + t * 8 + col_in;
        *(float2*)&ctx[(size_t)(b * S_LEN + row_lo) * DMODEL + col] =
            make_float2(o[t][0] * inv0, o[t][1] * inv0);
        *(float2*)&ctx[(size_t)(b * S_LEN + row_lo + 8) * DMODEL + col] =
            make_float2(o[t][2] * inv1, o[t][3] * inv1);
    }
}

// ---------------------------------------------------------------------------
extern "C" void kernel_launch(void* const* d_in, const int* in_sizes, int n_in,
                              void* d_out, int out_size)
{
    const float* x      = (const float*)d_in[0];  // [2,2048,1024]
    const float* w_qkv  = (const float*)d_in[1];  // [3072,1024]
    const float* w_proj = (const float*)d_in[2];  // [1024,1024]
    const float* b_proj = (const float*)d_in[3];  // [1024]
    float* out = (float*)d_out;                   // [2,2048,1024]

    float *qkv, *ctx;
    cudaGetSymbolAddress((void**)&qkv, g_qkv);
    cudaGetSymbolAddress((void**)&ctx, g_ctx);
    __nv_bfloat16 *xhi, *xlo, *wqh, *wql, *chi, *clo, *wph, *wpl;
    cudaGetSymbolAddress((void**)&xhi, g_xhi);
    cudaGetSymbolAddress((void**)&xlo, g_xlo);
    cudaGetSymbolAddress((void**)&wqh, g_wqh);
    cudaGetSymbolAddress((void**)&wql, g_wql);
    cudaGetSymbolAddress((void**)&chi, g_chi);
    cudaGetSymbolAddress((void**)&clo, g_clo);
    cudaGetSymbolAddress((void**)&wph, g_wph);
    cudaGetSymbolAddress((void**)&wpl, g_wpl);

    cudaFuncSetAttribute(attn_mma, cudaFuncAttributeMaxDynamicSharedMemorySize, ATTN_SMEM);
    cudaFuncSetAttribute(mma_gemm<false>, cudaFuncAttributeMaxDynamicSharedMemorySize, GEMM_SMEM);
    cudaFuncSetAttribute(mma_gemm<true>,  cudaFuncAttributeMaxDynamicSharedMemorySize, GEMM_SMEM);

    // Split inputs to bf16 hi/lo
    split_fp32<<<(MTOT * DMODEL / 4) / 256, 256>>>(x, xhi, xlo);
    split_fp32<<<(TRIPLE * DMODEL / 4) / 256, 256>>>(w_qkv, wqh, wql);
    split_fp32<<<(DMODEL * DMODEL / 4) / 256, 256>>>(w_proj, wph, wpl);

    // 1) QKV projection (tensor cores, split bf16)
    {
        dim3 grid(TRIPLE / GBN, MTOT / GBM);
        mma_gemm<false><<<grid, 256, GEMM_SMEM>>>(xhi, xlo, wqh, wql, nullptr, qkv,
                                                  MTOT, TRIPLE, DMODEL);
    }
    // 2) Causal flash attention (tensor cores, split bf16)
    {
        dim3 grid(S_LEN / 64, BATCH * NHEAD);
        attn_mma<<<grid, 128, ATTN_SMEM>>>(qkv, ctx);
    }
    // 3) Output projection (tensor cores, split bf16, bias)
    split_fp32<<<(MTOT * DMODEL / 4) / 256, 256>>>(ctx, chi, clo);
    {
        dim3 grid(DMODEL / GBN, MTOT / GBM);
        mma_gemm<true><<<grid, 256, GEMM_SMEM>>>(chi, clo, wph, wpl, b_proj, out,
                                                 MTOT, DMODEL, DMODEL);
    }
}

// round 7
// speedup vs baseline: 3.1933x; 1.0978x over previous
#include <cuda_runtime.h>
#include <cuda_bf16.h>
#include <cstdint>

#define BATCH   2
#define S_LEN   2048
#define DMODEL  1024
#define NHEAD   16
#define DHEAD   64
#define TRIPLE  (3 * DMODEL)    // 3072
#define MTOT    (BATCH * S_LEN) // 4096

// ---------------------------------------------------------------------------
// Scratch (allocation-free: __device__ globals)
// ---------------------------------------------------------------------------
__device__ float g_qkv[(size_t)MTOT * TRIPLE];   // fp32 QKV output
__device__ float g_ctx[(size_t)MTOT * DMODEL];   // fp32 attention output

__device__ __nv_bfloat16 g_xhi[(size_t)MTOT * DMODEL];
__device__ __nv_bfloat16 g_xlo[(size_t)MTOT * DMODEL];
__device__ __nv_bfloat16 g_wqh[(size_t)TRIPLE * DMODEL];
__device__ __nv_bfloat16 g_wql[(size_t)TRIPLE * DMODEL];
__device__ __nv_bfloat16 g_chi[(size_t)MTOT * DMODEL];
__device__ __nv_bfloat16 g_clo[(size_t)MTOT * DMODEL];
__device__ __nv_bfloat16 g_wph[(size_t)DMODEL * DMODEL];
__device__ __nv_bfloat16 g_wpl[(size_t)DMODEL * DMODEL];

// ---------------------------------------------------------------------------
// PTX helpers (Ampere-class: legal on sm_103)
// ---------------------------------------------------------------------------
__device__ __forceinline__ void cp_async16(uint32_t dst, const void* src) {
    asm volatile("cp.async.cg.shared.global [%0], [%1], 16;"
                 :: "r"(dst), "l"(__cvta_generic_to_global(src)));
}
__device__ __forceinline__ void cp_commit() {
    asm volatile("cp.async.commit_group;" ::: "memory");
}
template <int N> __device__ __forceinline__ void cp_wait() {
    asm volatile("cp.async.wait_group %0;" :: "n"(N) : "memory");
}
__device__ __forceinline__ void ldsm_x4(uint32_t* r, uint32_t addr) {
    asm volatile("ldmatrix.sync.aligned.m8n8.x4.shared.b16 {%0,%1,%2,%3}, [%4];"
                 : "=r"(r[0]), "=r"(r[1]), "=r"(r[2]), "=r"(r[3]) : "r"(addr));
}
__device__ __forceinline__ void ldsm_x2(uint32_t* r, uint32_t addr) {
    asm volatile("ldmatrix.sync.aligned.m8n8.x2.shared.b16 {%0,%1}, [%2];"
                 : "=r"(r[0]), "=r"(r[1]) : "r"(addr));
}
__device__ __forceinline__ void ldsm_x2t(uint32_t* r, uint32_t addr) {
    asm volatile("ldmatrix.sync.aligned.m8n8.x2.trans.shared.b16 {%0,%1}, [%2];"
                 : "=r"(r[0]), "=r"(r[1]) : "r"(addr));
}
__device__ __forceinline__ void mma_bf16(float* d, const uint32_t* a, const uint32_t* b) {
    asm volatile("mma.sync.aligned.m16n8k16.row.col.f32.bf16.bf16.f32 "
                 "{%0,%1,%2,%3}, {%4,%5,%6,%7}, {%8,%9}, {%0,%1,%2,%3};"
                 : "+f"(d[0]), "+f"(d[1]), "+f"(d[2]), "+f"(d[3])
                 : "r"(a[0]), "r"(a[1]), "r"(a[2]), "r"(a[3]), "r"(b[0]), "r"(b[1]));
}
__device__ __forceinline__ uint32_t pack_bf2(float a, float b) {
    __nv_bfloat162 t = __float22bfloat162_rn(make_float2(a, b));
    return *(uint32_t*)&t;
}

// ---------------------------------------------------------------------------
// fp32 -> (hi, lo) bf16 split, 4 elems/thread
// ---------------------------------------------------------------------------
__global__ void __launch_bounds__(256) split_fp32(const float* __restrict__ in,
                                                  __nv_bfloat16* __restrict__ hi,
                                                  __nv_bfloat16* __restrict__ lo) {
    int i = blockIdx.x * 256 + threadIdx.x;
    float4 v = ((const float4*)in)[i];
    __nv_bfloat16 h0 = __float2bfloat16(v.x);
    __nv_bfloat16 h1 = __float2bfloat16(v.y);
    __nv_bfloat16 h2 = __float2bfloat16(v.z);
    __nv_bfloat16 h3 = __float2bfloat16(v.w);
    __nv_bfloat16 l0 = __float2bfloat16(v.x - __bfloat162float(h0));
    __nv_bfloat16 l1 = __float2bfloat16(v.y - __bfloat162float(h1));
    __nv_bfloat16 l2 = __float2bfloat16(v.z - __bfloat162float(h2));
    __nv_bfloat16 l3 = __float2bfloat16(v.w - __bfloat162float(h3));
    __nv_bfloat162* H = (__nv_bfloat162*)hi;
    __nv_bfloat162* L = (__nv_bfloat162*)lo;
    H[2 * i]     = __nv_bfloat162(h0, h1);
    H[2 * i + 1] = __nv_bfloat162(h2, h3);
    L[2 * i]     = __nv_bfloat162(l0, l1);
    L[2 * i + 1] = __nv_bfloat162(l2, l3);
}

// ---------------------------------------------------------------------------
// mma.sync split-bf16 GEMM: 128x128x32 CTA tile, 2 CTAs/SM.
// 3-stage cp.async pipeline, ONE __syncthreads per K-chunk.
// Smem tiles: 128 rows x 64B (no pad) with XOR swizzle:
//   phys_chunk = kc ^ ((row >> 1) & 3)   (16B chunks, 4 per row)
// ---------------------------------------------------------------------------
#define GBM 128
#define GBN 128
#define GBK 32
#define TILEB (128 * 64)            // 8192 bytes per operand tile
#define STAGEB (4 * TILEB)          // Ah, Al, Bh, Bl = 32768
#define NSTAGE 3
#define GEMM_SMEM (NSTAGE * STAGEB) // 98304

__device__ __forceinline__ uint32_t sw_off(int row, int kc) {
    return (uint32_t)(row * 64 + ((kc ^ ((row >> 1) & 3)) << 4));
}

template <bool BIAS>
__global__ void __launch_bounds__(256, 2)
mma_gemm(const __nv_bfloat16* __restrict__ Ah, const __nv_bfloat16* __restrict__ Al,
         const __nv_bfloat16* __restrict__ Bh, const __nv_bfloat16* __restrict__ Bl,
         const float* __restrict__ bias, float* __restrict__ C,
         int M, int N, int K)
{
    extern __shared__ char smem[];
    const uint32_t sb = (uint32_t)__cvta_generic_to_shared(smem);
    const int tid = threadIdx.x, wid = tid >> 5, lane = tid & 31;
    const int wm = wid >> 2, wn = wid & 3;
    const int bm = blockIdx.y * GBM, bn = blockIdx.x * GBN;
    const int NK = K / GBK;

    auto load_stage = [&](int s, int kc_blk) {
        uint32_t base = sb + s * STAGEB;
        int k0 = kc_blk * GBK;
        #pragma unroll
        for (int t = 0; t < 2; t++) {
            int id = tid + t * 256;              // 0..511
            int row = id >> 2, kc = id & 3;      // row 0..127, chunk 0..3
            uint32_t dst = base + sw_off(row, kc);
            size_t aoff = (size_t)(bm + row) * K + k0 + kc * 8;
            size_t boff = (size_t)(bn + row) * K + k0 + kc * 8;
            cp_async16(dst,              Ah + aoff);
            cp_async16(dst + TILEB,      Al + aoff);
            cp_async16(dst + 2 * TILEB,  Bh + boff);
            cp_async16(dst + 3 * TILEB,  Bl + boff);
        }
        cp_commit();
    };

    // Prologue: stages 0 and 1
    load_stage(0, 0);
    load_stage(1, 1);

    float acc[4][4][4];
    #pragma unroll
    for (int i = 0; i < 4; i++)
        #pragma unroll
        for (int j = 0; j < 4; j++)
            #pragma unroll
            for (int r = 0; r < 4; r++) acc[i][j][r] = 0.f;

    // Per-lane ldmatrix row indices (swizzle xor precomputable per row)
    const int rowA0 = wm * 64 + (lane & 15);     // + mt*16
    const int kcA   = lane >> 4;                 // + kk*2
    const int l16 = lane & 15;
    const int rowB0 = wn * 32 + (l16 & 7);       // + nt*8
    const int kcB   = l16 >> 3;                  // + kk*2

    for (int i = 0; i < NK; i++) {
        const int s = i % NSTAGE;
        cp_wait<1>();
        __syncthreads();
        if (i + 2 < NK) load_stage((i + 2) % NSTAGE, i + 2);

        const uint32_t base = sb + s * STAGEB;
        #pragma unroll
        for (int kk = 0; kk < 2; kk++) {
            uint32_t ah[4][4], al[4][4], bh[4][2], bl[4][2];
            #pragma unroll
            for (int mt = 0; mt < 4; mt++) {
                uint32_t ad = base + sw_off(rowA0 + mt * 16, kcA + kk * 2);
                ldsm_x4(ah[mt], ad);
                ldsm_x4(al[mt], ad + TILEB);
            }
            #pragma unroll
            for (int nt = 0; nt < 4; nt++) {
                uint32_t bd = base + 2 * TILEB + sw_off(rowB0 + nt * 8, kcB + kk * 2);
                ldsm_x2(bh[nt], bd);
                ldsm_x2(bl[nt], bd + TILEB);
            }
            #pragma unroll
            for (int mt = 0; mt < 4; mt++)
                #pragma unroll
                for (int nt = 0; nt < 4; nt++)
                    mma_bf16(acc[mt][nt], ah[mt], bh[nt]);
            #pragma unroll
            for (int mt = 0; mt < 4; mt++)
                #pragma unroll
                for (int nt = 0; nt < 4; nt++)
                    mma_bf16(acc[mt][nt], ah[mt], bl[nt]);
            #pragma unroll
            for (int mt = 0; mt < 4; mt++)
                #pragma unroll
                for (int nt = 0; nt < 4; nt++)
                    mma_bf16(acc[mt][nt], al[mt], bh[nt]);
        }
    }

    #pragma unroll
    for (int mt = 0; mt < 4; mt++) {
        #pragma unroll
        for (int nt = 0; nt < 4; nt++) {
            int row = bm + wm * 64 + mt * 16 + (lane >> 2);
            int col = bn + wn * 32 + nt * 8 + (lane & 3) * 2;
            float b0 = 0.f, b1 = 0.f;
            if (BIAS) { b0 = bias[col]; b1 = bias[col + 1]; }
            float2 v0 = make_float2(acc[mt][nt][0] + b0, acc[mt][nt][1] + b1);
            float2 v1 = make_float2(acc[mt][nt][2] + b0, acc[mt][nt][3] + b1);
            *(float2*)&C[(size_t)row * N + col] = v0;
            *(float2*)&C[(size_t)(row + 8) * N + col] = v1;
        }
    }
}

// ---------------------------------------------------------------------------
// Flash attention (causal) on mma.sync bf16 with split precision (as R5/R6).
// ---------------------------------------------------------------------------
#define AROWP 72
#define AROWBY (AROWP * 2)           // 144 bytes
#define ATILE  (64 * AROWP)
#define ATTN_SMEM (6 * ATILE * 2)    // 55296 bytes

__global__ void __launch_bounds__(128) attn_mma(const float* __restrict__ qkv,
                                                float* __restrict__ ctx)
{
    extern __shared__ __nv_bfloat16 as[];
    __nv_bfloat16* Qh = as;
    __nv_bfloat16* Ql = as + ATILE;
    __nv_bfloat16* Kh = as + 2 * ATILE;
    __nv_bfloat16* Kl = as + 3 * ATILE;
    __nv_bfloat16* Vh = as + 4 * ATILE;
    __nv_bfloat16* Vl = as + 5 * ATILE;
    const uint32_t sQh = (uint32_t)__cvta_generic_to_shared(Qh);
    const uint32_t sQl = (uint32_t)__cvta_generic_to_shared(Ql);
    const uint32_t sKh = (uint32_t)__cvta_generic_to_shared(Kh);
    const uint32_t sKl = (uint32_t)__cvta_generic_to_shared(Kl);
    const uint32_t sVh = (uint32_t)__cvta_generic_to_shared(Vh);
    const uint32_t sVl = (uint32_t)__cvta_generic_to_shared(Vl);

    const int mblk = blockIdx.x, bh = blockIdx.y;
    const int b = bh >> 4, h = bh & 15;
    const int tid = threadIdx.x, wid = tid >> 5, lane = tid & 31;
    const int l16 = lane & 15;
    const int m0 = mblk * 64;
    const float scale = 0.125f;

    #pragma unroll
    for (int l = 0; l < 8; l++) {
        int id = tid + l * 128;
        int row = id >> 4, c4 = (id & 15) << 2;
        float4 v = *(const float4*)&qkv[(size_t)(b * S_LEN + m0 + row) * TRIPLE + h * DHEAD + c4];
        float h0 = __bfloat162float(__float2bfloat16(v.x));
        float h1 = __bfloat162float(__float2bfloat16(v.y));
        float h2 = __bfloat162float(__float2bfloat16(v.z));
        float h3 = __bfloat162float(__float2bfloat16(v.w));
        int off = row * AROWP + c4;
        *(__nv_bfloat162*)&Qh[off]     = __floats2bfloat162_rn(h0, h1);
        *(__nv_bfloat162*)&Qh[off + 2] = __floats2bfloat162_rn(h2, h3);
        *(__nv_bfloat162*)&Ql[off]     = __floats2bfloat162_rn(v.x - h0, v.y - h1);
        *(__nv_bfloat162*)&Ql[off + 2] = __floats2bfloat162_rn(v.z - h2, v.w - h3);
    }

    float o[8][4];
    #pragma unroll
    for (int t = 0; t < 8; t++)
        #pragma unroll
        for (int r = 0; r < 4; r++) o[t][r] = 0.f;
    float m_i[2] = {-1e30f, -1e30f}, l_i[2] = {0.f, 0.f};

    const int row_lo = m0 + wid * 16 + (lane >> 2);
    const int col_in = (lane & 3) * 2;

    for (int nb = 0; nb <= mblk; nb++) {
        const int n0 = nb * 64;
        __syncthreads();

        #pragma unroll
        for (int l = 0; l < 8; l++) {
            int id = tid + l * 128;
            int row = id >> 4, c4 = (id & 15) << 2;
            size_t base = (size_t)(b * S_LEN + n0 + row) * TRIPLE + h * DHEAD + c4;
            int off = row * AROWP + c4;
            float4 kv = *(const float4*)&qkv[base + DMODEL];
            float kh0 = __bfloat162float(__float2bfloat16(kv.x));
            float kh1 = __bfloat162float(__float2bfloat16(kv.y));
            float kh2 = __bfloat162float(__float2bfloat16(kv.z));
            float kh3 = __bfloat162float(__float2bfloat16(kv.w));
            *(__nv_bfloat162*)&Kh[off]     = __floats2bfloat162_rn(kh0, kh1);
            *(__nv_bfloat162*)&Kh[off + 2] = __floats2bfloat162_rn(kh2, kh3);
            *(__nv_bfloat162*)&Kl[off]     = __floats2bfloat162_rn(kv.x - kh0, kv.y - kh1);
            *(__nv_bfloat162*)&Kl[off + 2] = __floats2bfloat162_rn(kv.z - kh2, kv.w - kh3);
            float4 vv = *(const float4*)&qkv[base + 2 * DMODEL];
            float vh0 = __bfloat162float(__float2bfloat16(vv.x));
            float vh1 = __bfloat162float(__float2bfloat16(vv.y));
            float vh2 = __bfloat162float(__float2bfloat16(vv.z));
            float vh3 = __bfloat162float(__float2bfloat16(vv.w));
            *(__nv_bfloat162*)&Vh[off]     = __floats2bfloat162_rn(vh0, vh1);
            *(__nv_bfloat162*)&Vh[off + 2] = __floats2bfloat162_rn(vh2, vh3);
            *(__nv_bfloat162*)&Vl[off]     = __floats2bfloat162_rn(vv.x - vh0, vv.y - vh1);
            *(__nv_bfloat162*)&Vl[off + 2] = __floats2bfloat162_rn(vv.z - vh2, vv.w - vh3);
        }
        __syncthreads();

        float s[8][4];
        #pragma unroll
        for (int t = 0; t < 8; t++)
            #pragma unroll
            for (int r = 0; r < 4; r++) s[t][r] = 0.f;

        #pragma unroll
        for (int kk = 0; kk < 4; kk++) {
            uint32_t qh4[4], ql4[4];
            uint32_t qaddr = (wid * 16 + (lane & 15)) * AROWBY + (lane >> 4) * 16 + kk * 32;
            ldsm_x4(qh4, sQh + qaddr);
            ldsm_x4(ql4, sQl + qaddr);
            #pragma unroll
            for (int t = 0; t < 8; t++) {
                uint32_t kaddr = (t * 8 + (l16 & 7)) * AROWBY + (l16 >> 3) * 16 + kk * 32;
                uint32_t kh2r[2], kl2r[2];
                ldsm_x2(kh2r, sKh + kaddr);
                ldsm_x2(kl2r, sKl + kaddr);
                mma_bf16(s[t], qh4, kh2r);
                mma_bf16(s[t], qh4, kl2r);
                mma_bf16(s[t], ql4, kh2r);
            }
        }

        if (nb == mblk) {
            #pragma unroll
            for (int t = 0; t < 8; t++) {
                int c0g = n0 + t * 8 + col_in;
                s[t][0] = (c0g     > row_lo)     ? -1e30f : s[t][0] * scale;
                s[t][1] = (c0g + 1 > row_lo)     ? -1e30f : s[t][1] * scale;
                s[t][2] = (c0g     > row_lo + 8) ? -1e30f : s[t][2] * scale;
                s[t][3] = (c0g + 1 > row_lo + 8) ? -1e30f : s[t][3] * scale;
            }
        } else {
            #pragma unroll
            for (int t = 0; t < 8; t++)
                #pragma unroll
                for (int r = 0; r < 4; r++) s[t][r] *= scale;
        }

        float mx0 = -1e30f, mx1 = -1e30f;
        #pragma unroll
        for (int t = 0; t < 8; t++) {
            mx0 = fmaxf(mx0, fmaxf(s[t][0], s[t][1]));
            mx1 = fmaxf(mx1, fmaxf(s[t][2], s[t][3]));
        }
        #pragma unroll
        for (int off = 1; off <= 2; off <<= 1) {
            mx0 = fmaxf(mx0, __shfl_xor_sync(0xffffffffu, mx0, off));
            mx1 = fmaxf(mx1, __shfl_xor_sync(0xffffffffu, mx1, off));
        }
        float mn0 = fmaxf(m_i[0], mx0), mn1 = fmaxf(m_i[1], mx1);
        float al0 = __expf(m_i[0] - mn0), al1 = __expf(m_i[1] - mn1);
        m_i[0] = mn0; m_i[1] = mn1;

        float sum0 = 0.f, sum1 = 0.f;
        #pragma unroll
        for (int t = 0; t < 8; t++) {
            s[t][0] = __expf(s[t][0] - mn0);
            s[t][1] = __expf(s[t][1] - mn0);
            s[t][2] = __expf(s[t][2] - mn1);
            s[t][3] = __expf(s[t][3] - mn1);
            sum0 += s[t][0] + s[t][1];
            sum1 += s[t][2] + s[t][3];
        }
        #pragma unroll
        for (int off = 1; off <= 2; off <<= 1) {
            sum0 += __shfl_xor_sync(0xffffffffu, sum0, off);
            sum1 += __shfl_xor_sync(0xffffffffu, sum1, off);
        }
        l_i[0] = l_i[0] * al0 + sum0;
        l_i[1] = l_i[1] * al1 + sum1;
        #pragma unroll
        for (int t = 0; t < 8; t++) {
            o[t][0] *= al0; o[t][1] *= al0;
            o[t][2] *= al1; o[t][3] *= al1;
        }

        #pragma unroll
        for (int kk = 0; kk < 4; kk++) {
            const int ta = 2 * kk, tb = 2 * kk + 1;
            uint32_t ph[4], pl[4];
            ph[0] = pack_bf2(s[ta][0], s[ta][1]);
            ph[1] = pack_bf2(s[ta][2], s[ta][3]);
            ph[2] = pack_bf2(s[tb][0], s[tb][1]);
            ph[3] = pack_bf2(s[tb][2], s[tb][3]);
            {
                __nv_bfloat162 h0 = *(__nv_bfloat162*)&ph[0];
                __nv_bfloat162 h1 = *(__nv_bfloat162*)&ph[1];
                __nv_bfloat162 h2 = *(__nv_bfloat162*)&ph[2];
                __nv_bfloat162 h3 = *(__nv_bfloat162*)&ph[3];
                pl[0] = pack_bf2(s[ta][0] - __bfloat162float(h0.x), s[ta][1] - __bfloat162float(h0.y));
                pl[1] = pack_bf2(s[ta][2] - __bfloat162float(h1.x), s[ta][3] - __bfloat162float(h1.y));
                pl[2] = pack_bf2(s[tb][0] - __bfloat162float(h2.x), s[tb][1] - __bfloat162float(h2.y));
                pl[3] = pack_bf2(s[tb][2] - __bfloat162float(h3.x), s[tb][3] - __bfloat162float(h3.y));
            }
            #pragma unroll
            for (int t = 0; t < 8; t++) {
                uint32_t vaddr = (kk * 16 + l16) * AROWBY + t * 16;
                uint32_t vh2r[2], vl2r[2];
                ldsm_x2t(vh2r, sVh + vaddr);
                ldsm_x2t(vl2r, sVl + vaddr);
                mma_bf16(o[t], ph, vh2r);
                mma_bf16(o[t], ph, vl2r);
                mma_bf16(o[t], pl, vh2r);
            }
        }
    }

    float inv0 = 1.f / l_i[0], inv1 = 1.f / l_i[1];
    #pragma unroll
    for (int t = 0; t < 8; t++) {
        int col = h * DHEAD + t * 8 + col_in;
        *(float2*)&ctx[(size_t)(b * S_LEN + row_lo) * DMODEL + col] =
            make_float2(o[t][0] * inv0, o[t][1] * inv0);
        *(float2*)&ctx[(size_t)(b * S_LEN + row_lo + 8) * DMODEL + col] =
            make_float2(o[t][2] * inv1, o[t][3] * inv1);
    }
}

// ---------------------------------------------------------------------------
extern "C" void kernel_launch(void* const* d_in, const int* in_sizes, int n_in,
                              void* d_out, int out_size)
{
    const float* x      = (const float*)d_in[0];  // [2,2048,1024]
    const float* w_qkv  = (const float*)d_in[1];  // [3072,1024]
    const float* w_proj = (const float*)d_in[2];  // [1024,1024]
    const float* b_proj = (const float*)d_in[3];  // [1024]
    float* out = (float*)d_out;                   // [2,2048,1024]

    float *qkv, *ctx;
    cudaGetSymbolAddress((void**)&qkv, g_qkv);
    cudaGetSymbolAddress((void**)&ctx, g_ctx);
    __nv_bfloat16 *xhi, *xlo, *wqh, *wql, *chi, *clo, *wph, *wpl;
    cudaGetSymbolAddress((void**)&xhi, g_xhi);
    cudaGetSymbolAddress((void**)&xlo, g_xlo);
    cudaGetSymbolAddress((void**)&wqh, g_wqh);
    cudaGetSymbolAddress((void**)&wql, g_wql);
    cudaGetSymbolAddress((void**)&chi, g_chi);
    cudaGetSymbolAddress((void**)&clo, g_clo);
    cudaGetSymbolAddress((void**)&wph, g_wph);
    cudaGetSymbolAddress((void**)&wpl, g_wpl);

    cudaFuncSetAttribute(attn_mma, cudaFuncAttributeMaxDynamicSharedMemorySize, ATTN_SMEM);
    cudaFuncSetAttribute(mma_gemm<false>, cudaFuncAttributeMaxDynamicSharedMemorySize, GEMM_SMEM);
    cudaFuncSetAttribute(mma_gemm<true>,  cudaFuncAttributeMaxDynamicSharedMemorySize, GEMM_SMEM);

    // Split inputs to bf16 hi/lo
    split_fp32<<<(MTOT * DMODEL / 4) / 256, 256>>>(x, xhi, xlo);
    split_fp32<<<(TRIPLE * DMODEL / 4) / 256, 256>>>(w_qkv, wqh, wql);
    split_fp32<<<(DMODEL * DMODEL / 4) / 256, 256>>>(w_proj, wph, wpl);

    // 1) QKV projection (tensor cores, split bf16)
    {
        dim3 grid(TRIPLE / GBN, MTOT / GBM);
        mma_gemm<false><<<grid, 256, GEMM_SMEM>>>(xhi, xlo, wqh, wql, nullptr, qkv,
                                                  MTOT, TRIPLE, DMODEL);
    }
    // 2) Causal flash attention (tensor cores, split bf16)
    {
        dim3 grid(S_LEN / 64, BATCH * NHEAD);
        attn_mma<<<grid, 128, ATTN_SMEM>>>(qkv, ctx);
    }
    // 3) Output projection (tensor cores, split bf16, bias)
    split_fp32<<<(MTOT * DMODEL / 4) / 256, 256>>>(ctx, chi, clo);
    {
        dim3 grid(DMODEL / GBN, MTOT / GBM);
        mma_gemm<true><<<grid, 256, GEMM_SMEM>>>(chi, clo, wph, wpl, b_proj, out,
                                                 MTOT, DMODEL, DMODEL);
    }
}